// round 9
// baseline (speedup 1.0000x reference)
#include <cuda_runtime.h>
#include <cuda_fp16.h>
#include <mma.h>
#include <cstdint>

using namespace nvcuda;

// ---------------- problem constants ----------------
#define BATCH   8
#define CDIM    512
#define HWDIM   128
#define NWIN    2048
#define MTOT    131072
#define QKVN    1536
#define ATTN_SCALE 0.17677669529663687f   // 32^-0.5

// ---------------- scratch (device globals; no runtime alloc) ----------------
__device__ __half g_xw  [(size_t)MTOT * CDIM];
__device__ __half g_qkv [(size_t)MTOT * QKVN];
__device__ __half g_ctx [(size_t)MTOT * CDIM];
__device__ float  g_x1  [(size_t)MTOT * CDIM];
__device__ __half g_xn2 [(size_t)MTOT * CDIM];
__device__ __half g_h   [(size_t)MTOT * CDIM];
__device__ __half g_wqkv [CDIM * QKVN];   // [K,N]
__device__ __half g_wproj[CDIM * CDIM];   // [K,N]
__device__ __half g_w1   [CDIM * CDIM];   // [o,c] = [N,K]
__device__ __half g_w2   [CDIM * CDIM];
__device__ float  g_bias [16 * 64 * 64];  // expanded rel-pos bias [head][n][m]

// =====================================================================
// batched weight f32 -> f16 convert
// =====================================================================
__global__ __launch_bounds__(256)
void cvt_all_kernel(const float* __restrict__ w0, const float* __restrict__ w1,
                    const float* __restrict__ w2, const float* __restrict__ w3,
                    __half* __restrict__ o0, __half* __restrict__ o1,
                    __half* __restrict__ o2, __half* __restrict__ o3)
{
    int i = blockIdx.x * 256 + threadIdx.x;    // 0 .. 393215
    const float* in; __half* out; int idx;
    if (i < 196608)      { in = w0; out = o0; idx = i; }
    else if (i < 262144) { in = w1; out = o1; idx = i - 196608; }
    else if (i < 327680) { in = w2; out = o2; idx = i - 262144; }
    else                 { in = w3; out = o3; idx = i - 327680; }
    float4 v = ((const float4*)in)[idx];
    __half2* o = (__half2*)out + idx * 2;
    o[0] = __floats2half2_rn(v.x, v.y);
    o[1] = __floats2half2_rn(v.z, v.w);
}

// =====================================================================
// expand rel-pos bias table -> g_bias[head][n][m]
// =====================================================================
__global__ __launch_bounds__(256)
void bias_expand_kernel(const float* __restrict__ table, float* __restrict__ out)
{
    int idx = blockIdx.x * 256 + threadIdx.x;     // 0..65535
    int m = idx & 63;
    int n = (idx >> 6) & 63;
    int h = idx >> 12;
    int i1 = n >> 3, j1 = n & 7;
    int i2 = m >> 3, j2 = m & 7;
    int ridx = (i1 - i2 + 7) * 15 + (j1 - j2 + 7);
    out[idx] = table[ridx * 16 + h];
}

// =====================================================================
// prep: BN + layout transform -> half.
// window_mode=1: out[(win*64+pix)*512 + c]; 0: out[pixel*512 + c]
// =====================================================================
__global__ __launch_bounds__(256)
void prep_kernel(const float* __restrict__ in,
                 const float* __restrict__ gamma, const float* __restrict__ beta,
                 const float* __restrict__ mean,  const float* __restrict__ var,
                 __half* __restrict__ out, int window_mode)
{
    __shared__ float sscale[CDIM];
    __shared__ float sshift[CDIM];
    __shared__ float tile[64][65];

    int bx  = blockIdx.x;
    int b   = bx >> 8;
    int hb  = (bx >> 4) & 15;
    int wb  = bx & 15;
    int tid = threadIdx.x;

    for (int c = tid; c < CDIM; c += 256) {
        float inv = rsqrtf(var[c] + 1e-5f);
        float sc  = gamma[c] * inv;
        sscale[c] = sc;
        sshift[c] = beta[c] - mean[c] * sc;
    }
    __syncthreads();

    int h0 = hb * 8, w0 = wb * 8;
    for (int cc = 0; cc < CDIM; cc += 64) {
        #pragma unroll
        for (int it = 0; it < 16; ++it) {
            int idx = it * 256 + tid;
            int cl  = idx >> 6;
            int pix = idx & 63;
            int c   = cc + cl;
            int i   = pix >> 3, j = pix & 7;
            float v = in[(((size_t)b * CDIM + c) * HWDIM + h0 + i) * HWDIM + w0 + j];
            tile[cl][pix] = v * sscale[c] + sshift[c];
        }
        __syncthreads();
        #pragma unroll
        for (int it = 0; it < 16; ++it) {
            int idx = it * 256 + tid;
            int pix = idx >> 6;
            int cl  = idx & 63;
            size_t dst;
            if (window_mode) {
                dst = ((size_t)bx * 64 + pix) * CDIM + cc + cl;
            } else {
                int i = pix >> 3, j = pix & 7;
                size_t p = ((size_t)b * HWDIM + h0 + i) * HWDIM + w0 + j;
                dst = p * CDIM + cc + cl;
            }
            out[dst] = __float2half(tile[cl][pix]);
        }
        __syncthreads();
    }
}

// =====================================================================
// persistent-A fp16 WMMA GEMM.
// One CTA owns a 128-row A block (full K=512 resident in smem) and loops
// over all N/128 column blocks, streaming B in 64-K chunks (2 stages).
// 4 warps (2m x 2n), warp tile 64x64.
// EPI: 0 bias->half; 1 bias+GELU->half; 2 bias+res->NCHW f32;
//      3 bias + window-reverse + x residual -> NCHW f32 (proj -> x1).
// =====================================================================
#define A_LDP 520                            // 512 + 8 pad (halfs)
#define AS_BYTES (128 * A_LDP * 2)           // 133120
#define BSTG 18432                           // per stage (both layouts fit)
#define B_OFF AS_BYTES
#define STAGE_OFF (AS_BYTES + 2 * BSTG)      // 169984
#define STG_LD 132
#define SMEMP (STAGE_OFF + 64 * STG_LD * 4)  // 203776
#define A_LD 72
#define B_LD_ROW 136

__device__ __forceinline__ void cp_async16(void* dst, const void* src) {
    unsigned int d = (unsigned int)__cvta_generic_to_shared(dst);
    asm volatile("cp.async.cg.shared.global [%0], [%1], 16;\n" :: "r"(d), "l"(src));
}
__device__ __forceinline__ void cp_commit() { asm volatile("cp.async.commit_group;\n"); }
template<int W> __device__ __forceinline__ void cp_wait() {
    asm volatile("cp.async.wait_group %0;\n" :: "n"(W));
}

template<bool B_COL, int EPI>
__global__ __launch_bounds__(128, 1)
void gemm_p(const __half* __restrict__ A, const __half* __restrict__ Bm,
            const float* __restrict__ bias, void* __restrict__ Cv,
            const float* __restrict__ res, int M, int N, int K)
{
    extern __shared__ __align__(16) unsigned char smem[];
    __half* As = (__half*)smem;

    int tid  = threadIdx.x;
    int warp = tid >> 5;
    int wm   = warp >> 1;          // 0..1
    int wn   = warp & 1;           // 0..1
    int m0   = blockIdx.y * 128;
    const int NBLK = N >> 7;
    const int T = NBLK * 8;        // total 64-K chunks across all N blocks

    auto loadB = [&](int g, int s) {
        __half* Bs = (__half*)(smem + B_OFF + s * BSTG);
        int nb = g >> 3;
        int k0 = (g & 7) * 64;
        int n0 = nb * 128;
        if (B_COL) {
            #pragma unroll
            for (int it = 0; it < 8; ++it) {
                int idx = it * 128 + tid;
                int r = idx >> 3, c8 = idx & 7;
                cp_async16(Bs + r * A_LD + c8 * 8, Bm + (size_t)(n0 + r) * K + k0 + c8 * 8);
            }
        } else {
            #pragma unroll
            for (int it = 0; it < 8; ++it) {
                int idx = it * 128 + tid;
                int r = idx >> 4, c8 = idx & 15;
                cp_async16(Bs + r * B_LD_ROW + c8 * 8, Bm + (size_t)(k0 + r) * N + n0 + c8 * 8);
            }
        }
    };

    // A full-block load (128 x 512 halfs = 8192 x 16B) + first B chunk, one group
    #pragma unroll
    for (int it = 0; it < 64; ++it) {
        int idx = it * 128 + tid;
        int r = idx >> 6, c = idx & 63;
        cp_async16(As + r * A_LDP + c * 8, A + (size_t)(m0 + r) * K + c * 8);
    }
    loadB(0, 0);
    cp_commit();

    wmma::fragment<wmma::accumulator, 16, 16, 16, float> acc[4][4];
    #pragma unroll
    for (int i = 0; i < 4; ++i)
        #pragma unroll
        for (int j = 0; j < 4; ++j)
            wmma::fill_fragment(acc[i][j], 0.0f);

    for (int g = 0; g < T; ++g) {
        cp_wait<0>();
        __syncthreads();
        if (g + 1 < T) { loadB(g + 1, (g + 1) & 1); cp_commit(); }

        const __half* Bs = (const __half*)(smem + B_OFF + (g & 1) * BSTG);
        int k0 = (g & 7) * 64;

        #pragma unroll
        for (int kk = 0; kk < 4; ++kk) {
            wmma::fragment<wmma::matrix_a, 16, 16, 16, __half, wmma::row_major> af[4];
            #pragma unroll
            for (int i = 0; i < 4; ++i)
                wmma::load_matrix_sync(af[i], As + (size_t)(wm * 64 + i * 16) * A_LDP + k0 + kk * 16, A_LDP);
            #pragma unroll
            for (int j = 0; j < 4; ++j) {
                if (B_COL) {
                    wmma::fragment<wmma::matrix_b, 16, 16, 16, __half, wmma::col_major> bf;
                    wmma::load_matrix_sync(bf, Bs + (wn * 64 + j * 16) * A_LD + kk * 16, A_LD);
                    #pragma unroll
                    for (int i = 0; i < 4; ++i)
                        wmma::mma_sync(acc[i][j], af[i], bf, acc[i][j]);
                } else {
                    wmma::fragment<wmma::matrix_b, 16, 16, 16, __half, wmma::row_major> bf;
                    wmma::load_matrix_sync(bf, Bs + (kk * 16) * B_LD_ROW + wn * 64 + j * 16, B_LD_ROW);
                    #pragma unroll
                    for (int i = 0; i < 4; ++i)
                        wmma::mma_sync(acc[i][j], af[i], bf, acc[i][j]);
                }
            }
        }

        if ((g & 7) == 7) {
            // ------------- epilogue for N-block nb -------------
            int nb = g >> 3;
            int n0 = nb * 128;
            float* stg = (float*)(smem + STAGE_OFF);     // [64][STG_LD]
            #pragma unroll
            for (int p = 0; p < 2; ++p) {
                __syncthreads();                          // all MMAs done / stage free
                if (wm == p) {
                    #pragma unroll
                    for (int i = 0; i < 4; ++i)
                        #pragma unroll
                        for (int j = 0; j < 4; ++j)
                            wmma::store_matrix_sync(stg + (i * 16) * STG_LD + wn * 64 + j * 16,
                                                    acc[i][j], STG_LD, wmma::mem_row_major);
                }
                __syncthreads();
                #pragma unroll
                for (int it = 0; it < 8; ++it) {
                    int e = it * 1024 + tid * 8;          // 0..8191
                    if (EPI == 2) {
                        int r = e & 63, col = e >> 6;     // r 8-consecutive
                        int n = n0 + col;
                        float bv = bias[n];
                        int m = m0 + p * 64 + r;
                        int bb = m >> 14, hw = m & 16383;
                        size_t oi = ((size_t)bb * CDIM + n) * 16384 + hw;
                        float4 o0, o1;
                        const float4 r0 = *(const float4*)(res + oi);
                        const float4 r1 = *(const float4*)(res + oi + 4);
                        o0.x = stg[(r+0)*STG_LD+col] + bv + r0.x;
                        o0.y = stg[(r+1)*STG_LD+col] + bv + r0.y;
                        o0.z = stg[(r+2)*STG_LD+col] + bv + r0.z;
                        o0.w = stg[(r+3)*STG_LD+col] + bv + r0.w;
                        o1.x = stg[(r+4)*STG_LD+col] + bv + r1.x;
                        o1.y = stg[(r+5)*STG_LD+col] + bv + r1.y;
                        o1.z = stg[(r+6)*STG_LD+col] + bv + r1.z;
                        o1.w = stg[(r+7)*STG_LD+col] + bv + r1.w;
                        *(float4*)((float*)Cv + oi)     = o0;
                        *(float4*)((float*)Cv + oi + 4) = o1;
                    } else {
                        int col = e & 127, r = e >> 7;    // col 8-aligned consecutive
                        int m = m0 + p * 64 + r;
                        int n = n0 + col;
                        float v[8];
                        #pragma unroll
                        for (int j = 0; j < 8; ++j) {
                            v[j] = stg[r * STG_LD + col + j] + bias[n + j];
                            if (EPI == 1)
                                v[j] = 0.5f * v[j] * (1.0f + erff(v[j] * 0.70710678118654752f));
                        }
                        if (EPI == 3) {
                            int bb  = m >> 14;
                            int wl  = (m >> 6) & 255;
                            int pix = m & 63;
                            int q = wl * 32768 + pix * 512 + n;
                            size_t base = (size_t)bb * 8388608 + (size_t)(q >> 14) * 16384
                                        + (((q >> 10) & 15) * 8 + ((q >> 3) & 7)) * 128
                                        + ((q >> 6) & 15) * 8;
                            const float4 x0 = *(const float4*)(res + base);
                            const float4 x1v = *(const float4*)(res + base + 4);
                            float4 o0 = make_float4(v[0]+x0.x, v[1]+x0.y, v[2]+x0.z, v[3]+x0.w);
                            float4 o1 = make_float4(v[4]+x1v.x, v[5]+x1v.y, v[6]+x1v.z, v[7]+x1v.w);
                            *(float4*)((float*)Cv + base)     = o0;
                            *(float4*)((float*)Cv + base + 4) = o1;
                        } else {
                            uint4 pk; __half2 hh;
                            hh = __floats2half2_rn(v[0], v[1]); pk.x = *(unsigned*)&hh;
                            hh = __floats2half2_rn(v[2], v[3]); pk.y = *(unsigned*)&hh;
                            hh = __floats2half2_rn(v[4], v[5]); pk.z = *(unsigned*)&hh;
                            hh = __floats2half2_rn(v[6], v[7]); pk.w = *(unsigned*)&hh;
                            *(uint4*)((__half*)Cv + (size_t)m * N + n) = pk;
                        }
                    }
                }
            }
            #pragma unroll
            for (int i = 0; i < 4; ++i)
                #pragma unroll
                for (int j = 0; j < 4; ++j)
                    wmma::fill_fragment(acc[i][j], 0.0f);
        }
    }
}

// =====================================================================
// tensor-core attention: one block per (window, head), 64 threads (2 warps).
// =====================================================================
#define QK_LD 40    // halfs
#define S_LD  68    // floats
#define P_LD  72    // halfs

__global__ __launch_bounds__(64)
void attn_tc_kernel(const __half* __restrict__ qkv, const float* __restrict__ bias16,
                    __half* __restrict__ ctx)
{
    __shared__ __align__(16) __half Qs[64 * QK_LD];
    __shared__ __align__(16) __half Ks[64 * QK_LD];
    __shared__ __align__(16) __half Vs[64 * QK_LD];
    __shared__ __align__(16) float  Ss[64 * S_LD];
    __shared__ __align__(16) __half Ps[64 * P_LD];

    int win  = blockIdx.x >> 4;
    int head = blockIdx.x & 15;
    int tid  = threadIdx.x;
    int warp = tid >> 5;

    size_t base = (size_t)win * 64 * QKVN + head * 32;
    #pragma unroll
    for (int i = 0; i < 4; ++i) {
        int idx = i * 64 + tid;
        int tok = idx >> 2, c = idx & 3;
        size_t off = base + (size_t)tok * QKVN + c * 8;
        *(uint4*)(Qs + tok * QK_LD + c * 8) = *(const uint4*)(qkv + off);
        *(uint4*)(Ks + tok * QK_LD + c * 8) = *(const uint4*)(qkv + off + 512);
        *(uint4*)(Vs + tok * QK_LD + c * 8) = *(const uint4*)(qkv + off + 1024);
    }
    __syncthreads();

    {
        wmma::fragment<wmma::accumulator, 16, 16, 16, float> sacc[2][4];
        #pragma unroll
        for (int i = 0; i < 2; ++i)
            #pragma unroll
            for (int j = 0; j < 4; ++j)
                wmma::fill_fragment(sacc[i][j], 0.0f);
        #pragma unroll
        for (int kk = 0; kk < 32; kk += 16) {
            wmma::fragment<wmma::matrix_a, 16, 16, 16, __half, wmma::row_major> af[2];
            wmma::fragment<wmma::matrix_b, 16, 16, 16, __half, wmma::col_major> bf[4];
            #pragma unroll
            for (int i = 0; i < 2; ++i)
                wmma::load_matrix_sync(af[i], Qs + (warp * 32 + i * 16) * QK_LD + kk, QK_LD);
            #pragma unroll
            for (int j = 0; j < 4; ++j)
                wmma::load_matrix_sync(bf[j], Ks + (j * 16) * QK_LD + kk, QK_LD);
            #pragma unroll
            for (int i = 0; i < 2; ++i)
                #pragma unroll
                for (int j = 0; j < 4; ++j)
                    wmma::mma_sync(sacc[i][j], af[i], bf[j], sacc[i][j]);
        }
        #pragma unroll
        for (int i = 0; i < 2; ++i)
            #pragma unroll
            for (int j = 0; j < 4; ++j)
                wmma::store_matrix_sync(Ss + (warp * 32 + i * 16) * S_LD + j * 16,
                                        sacc[i][j], S_LD, wmma::mem_row_major);
    }
    __syncthreads();

    {
        int r = tid;
        const float* brow = bias16 + ((size_t)head * 64 + r) * 64;
        float v[64];
        float mx = -1e30f;
        #pragma unroll
        for (int q = 0; q < 16; ++q) {
            float4 s = *(float4*)(Ss + r * S_LD + q * 4);
            float4 b = *(const float4*)(brow + q * 4);
            v[q*4+0] = s.x * ATTN_SCALE + b.x;
            v[q*4+1] = s.y * ATTN_SCALE + b.y;
            v[q*4+2] = s.z * ATTN_SCALE + b.z;
            v[q*4+3] = s.w * ATTN_SCALE + b.w;
            mx = fmaxf(mx, fmaxf(fmaxf(v[q*4+0], v[q*4+1]), fmaxf(v[q*4+2], v[q*4+3])));
        }
        float sum = 0.0f;
        #pragma unroll
        for (int m = 0; m < 64; ++m) { v[m] = __expf(v[m] - mx); sum += v[m]; }
        float inv = 1.0f / sum;
        #pragma unroll
        for (int q = 0; q < 8; ++q) {
            uint4 pk; __half2 hh;
            hh = __floats2half2_rn(v[q*8+0]*inv, v[q*8+1]*inv); pk.x = *(unsigned*)&hh;
            hh = __floats2half2_rn(v[q*8+2]*inv, v[q*8+3]*inv); pk.y = *(unsigned*)&hh;
            hh = __floats2half2_rn(v[q*8+4]*inv, v[q*8+5]*inv); pk.z = *(unsigned*)&hh;
            hh = __floats2half2_rn(v[q*8+6]*inv, v[q*8+7]*inv); pk.w = *(unsigned*)&hh;
            *(uint4*)(Ps + r * P_LD + q * 8) = pk;
        }
    }
    __syncthreads();

    {
        wmma::fragment<wmma::accumulator, 16, 16, 16, float> oacc[2][2];
        #pragma unroll
        for (int i = 0; i < 2; ++i)
            #pragma unroll
            for (int j = 0; j < 2; ++j)
                wmma::fill_fragment(oacc[i][j], 0.0f);
        #pragma unroll
        for (int kk = 0; kk < 64; kk += 16) {
            wmma::fragment<wmma::matrix_a, 16, 16, 16, __half, wmma::row_major> af[2];
            wmma::fragment<wmma::matrix_b, 16, 16, 16, __half, wmma::row_major> bf[2];
            #pragma unroll
            for (int i = 0; i < 2; ++i)
                wmma::load_matrix_sync(af[i], Ps + (warp * 32 + i * 16) * P_LD + kk, P_LD);
            #pragma unroll
            for (int j = 0; j < 2; ++j)
                wmma::load_matrix_sync(bf[j], Vs + kk * QK_LD + j * 16, QK_LD);
            #pragma unroll
            for (int i = 0; i < 2; ++i)
                #pragma unroll
                for (int j = 0; j < 2; ++j)
                    wmma::mma_sync(oacc[i][j], af[i], bf[j], oacc[i][j]);
        }
        #pragma unroll
        for (int i = 0; i < 2; ++i)
            #pragma unroll
            for (int j = 0; j < 2; ++j)
                wmma::store_matrix_sync(Ss + (warp * 32 + i * 16) * S_LD + j * 16,
                                        oacc[i][j], S_LD, wmma::mem_row_major);
    }
    __syncthreads();

    {
        int r = tid;
        size_t ob = ((size_t)win * 64 + r) * CDIM + head * 32;
        #pragma unroll
        for (int q = 0; q < 4; ++q) {
            float4 a = *(float4*)(Ss + r * S_LD + q * 8);
            float4 b = *(float4*)(Ss + r * S_LD + q * 8 + 4);
            uint4 pk; __half2 hh;
            hh = __floats2half2_rn(a.x, a.y); pk.x = *(unsigned*)&hh;
            hh = __floats2half2_rn(a.z, a.w); pk.y = *(unsigned*)&hh;
            hh = __floats2half2_rn(b.x, b.y); pk.z = *(unsigned*)&hh;
            hh = __floats2half2_rn(b.z, b.w); pk.w = *(unsigned*)&hh;
            *(uint4*)(ctx + ob + q * 8) = pk;
        }
    }
}

// =====================================================================
extern "C" void kernel_launch(void* const* d_in, const int* in_sizes, int n_in,
                              void* d_out, int out_size)
{
    const float* x      = (const float*)d_in[0];
    const float* qkv_w  = (const float*)d_in[1];
    const float* qkv_b  = (const float*)d_in[2];
    const float* proj_w = (const float*)d_in[3];
    const float* proj_b = (const float*)d_in[4];
    const float* relt   = (const float*)d_in[5];
    const float* bn1g   = (const float*)d_in[6];
    const float* bn1b   = (const float*)d_in[7];
    const float* bn1m   = (const float*)d_in[8];
    const float* bn1v   = (const float*)d_in[9];
    const float* mlp_w1 = (const float*)d_in[10];
    const float* mlp_b1 = (const float*)d_in[11];
    const float* mlp_w2 = (const float*)d_in[12];
    const float* mlp_b2 = (const float*)d_in[13];
    const float* bn2g   = (const float*)d_in[14];
    const float* bn2b   = (const float*)d_in[15];
    const float* bn2m   = (const float*)d_in[16];
    const float* bn2v   = (const float*)d_in[17];
    float* out = (float*)d_out;

    __half *p_xw, *p_qkv, *p_ctx, *p_xn2, *p_h, *p_wqkv, *p_wproj, *p_w1, *p_w2;
    float  *p_x1, *p_bias;
    cudaGetSymbolAddress((void**)&p_xw,   g_xw);
    cudaGetSymbolAddress((void**)&p_qkv,  g_qkv);
    cudaGetSymbolAddress((void**)&p_ctx,  g_ctx);
    cudaGetSymbolAddress((void**)&p_x1,   g_x1);
    cudaGetSymbolAddress((void**)&p_xn2,  g_xn2);
    cudaGetSymbolAddress((void**)&p_h,    g_h);
    cudaGetSymbolAddress((void**)&p_wqkv, g_wqkv);
    cudaGetSymbolAddress((void**)&p_wproj,g_wproj);
    cudaGetSymbolAddress((void**)&p_w1,   g_w1);
    cudaGetSymbolAddress((void**)&p_w2,   g_w2);
    cudaGetSymbolAddress((void**)&p_bias, g_bias);

    cudaFuncSetAttribute(gemm_p<false, 0>, cudaFuncAttributeMaxDynamicSharedMemorySize, SMEMP);
    cudaFuncSetAttribute(gemm_p<false, 3>, cudaFuncAttributeMaxDynamicSharedMemorySize, SMEMP);
    cudaFuncSetAttribute(gemm_p<true, 1>,  cudaFuncAttributeMaxDynamicSharedMemorySize, SMEMP);
    cudaFuncSetAttribute(gemm_p<true, 2>,  cudaFuncAttributeMaxDynamicSharedMemorySize, SMEMP);

    // 0) weight conversions (batched) + bias expansion
    cvt_all_kernel<<<1536, 256>>>(qkv_w, proj_w, mlp_w1, mlp_w2,
                                  p_wqkv, p_wproj, p_w1, p_w2);
    bias_expand_kernel<<<256, 256>>>(relt, p_bias);

    // 1) BN1 + window partition
    prep_kernel<<<NWIN, 256>>>(x, bn1g, bn1b, bn1m, bn1v, p_xw, 1);

    // 2) QKV projection (persistent-A)
    gemm_p<false, 0><<<dim3(1, MTOT / 128), 128, SMEMP>>>(
        p_xw, p_wqkv, qkv_b, p_qkv, nullptr, MTOT, QKVN, CDIM);

    // 3) windowed attention (tensor cores)
    attn_tc_kernel<<<NWIN * 16, 64>>>(p_qkv, p_bias, p_ctx);

    // 4) proj + window-reverse + x residual -> x1 (NCHW f32), fused
    gemm_p<false, 3><<<dim3(1, MTOT / 128), 128, SMEMP>>>(
        p_ctx, p_wproj, proj_b, p_x1, x, MTOT, CDIM, CDIM);

    // 5) BN2 + pixel-major transpose
    prep_kernel<<<NWIN, 256>>>(p_x1, bn2g, bn2b, bn2m, bn2v, p_xn2, 0);

    // 6) FC1 + GELU
    gemm_p<true, 1><<<dim3(1, MTOT / 128), 128, SMEMP>>>(
        p_xn2, p_w1, mlp_b1, p_h, nullptr, MTOT, CDIM, CDIM);

    // 7) FC2 + bias + residual -> NCHW output
    gemm_p<true, 2><<<dim3(1, MTOT / 128), 128, SMEMP>>>(
        p_h, p_w2, mlp_b2, out, p_x1, MTOT, CDIM, CDIM);
}

// round 10
// speedup vs baseline: 1.0908x; 1.0908x over previous
#include <cuda_runtime.h>
#include <cuda_fp16.h>
#include <mma.h>
#include <cstdint>

using namespace nvcuda;

// ---------------- problem constants ----------------
#define BATCH   8
#define CDIM    512
#define HWDIM   128
#define NWIN    2048
#define MTOT    131072
#define QKVN    1536
#define ATTN_SCALE 0.17677669529663687f   // 32^-0.5

// ---------------- scratch (device globals; no runtime alloc) ----------------
__device__ __half g_xw  [(size_t)MTOT * CDIM];
__device__ __half g_qkv [(size_t)MTOT * QKVN];
__device__ __half g_ctx [(size_t)MTOT * CDIM];
__device__ __half g_x1  [(size_t)MTOT * CDIM];   // NCHW, half (round 10)
__device__ __half g_xn2 [(size_t)MTOT * CDIM];
__device__ __half g_h   [(size_t)MTOT * CDIM];
__device__ __half g_wqkv [CDIM * QKVN];   // [K,N]
__device__ __half g_wproj[CDIM * CDIM];   // [K,N]
__device__ __half g_w1   [CDIM * CDIM];   // [o,c] = [N,K]
__device__ __half g_w2   [CDIM * CDIM];
__device__ float  g_bias [16 * 64 * 64];  // expanded rel-pos bias [head][n][m]

// =====================================================================
// batched weight f32 -> f16 convert
// =====================================================================
__global__ __launch_bounds__(256)
void cvt_all_kernel(const float* __restrict__ w0, const float* __restrict__ w1,
                    const float* __restrict__ w2, const float* __restrict__ w3,
                    __half* __restrict__ o0, __half* __restrict__ o1,
                    __half* __restrict__ o2, __half* __restrict__ o3)
{
    int i = blockIdx.x * 256 + threadIdx.x;    // 0 .. 393215
    const float* in; __half* out; int idx;
    if (i < 196608)      { in = w0; out = o0; idx = i; }
    else if (i < 262144) { in = w1; out = o1; idx = i - 196608; }
    else if (i < 327680) { in = w2; out = o2; idx = i - 262144; }
    else                 { in = w3; out = o3; idx = i - 327680; }
    float4 v = ((const float4*)in)[idx];
    __half2* o = (__half2*)out + idx * 2;
    o[0] = __floats2half2_rn(v.x, v.y);
    o[1] = __floats2half2_rn(v.z, v.w);
}

// =====================================================================
// expand rel-pos bias table -> g_bias[head][n][m]
// =====================================================================
__global__ __launch_bounds__(256)
void bias_expand_kernel(const float* __restrict__ table, float* __restrict__ out)
{
    int idx = blockIdx.x * 256 + threadIdx.x;     // 0..65535
    int m = idx & 63;
    int n = (idx >> 6) & 63;
    int h = idx >> 12;
    int i1 = n >> 3, j1 = n & 7;
    int i2 = m >> 3, j2 = m & 7;
    int ridx = (i1 - i2 + 7) * 15 + (j1 - j2 + 7);
    out[idx] = table[ridx * 16 + h];
}

// =====================================================================
// prep: BN + layout transform -> half.
// window_mode=1: input f32, out[(win*64+pix)*512 + c]   (token-major)
// window_mode=0: input HALF, out[pixel*512 + c]         (pixel-major)
// =====================================================================
__global__ __launch_bounds__(256)
void prep_kernel(const void* __restrict__ in,
                 const float* __restrict__ gamma, const float* __restrict__ beta,
                 const float* __restrict__ mean,  const float* __restrict__ var,
                 __half* __restrict__ out, int window_mode)
{
    __shared__ float sscale[CDIM];
    __shared__ float sshift[CDIM];
    __shared__ float tile[64][65];

    const float*  in_f = (const float*)in;
    const __half* in_h = (const __half*)in;

    int bx  = blockIdx.x;
    int b   = bx >> 8;
    int hb  = (bx >> 4) & 15;
    int wb  = bx & 15;
    int tid = threadIdx.x;

    for (int c = tid; c < CDIM; c += 256) {
        float inv = rsqrtf(var[c] + 1e-5f);
        float sc  = gamma[c] * inv;
        sscale[c] = sc;
        sshift[c] = beta[c] - mean[c] * sc;
    }
    __syncthreads();

    int h0 = hb * 8, w0 = wb * 8;
    for (int cc = 0; cc < CDIM; cc += 64) {
        #pragma unroll
        for (int it = 0; it < 16; ++it) {
            int idx = it * 256 + tid;
            int cl  = idx >> 6;
            int pix = idx & 63;
            int c   = cc + cl;
            int i   = pix >> 3, j = pix & 7;
            size_t src = (((size_t)b * CDIM + c) * HWDIM + h0 + i) * HWDIM + w0 + j;
            float v = window_mode ? in_f[src] : __half2float(in_h[src]);
            tile[cl][pix] = v * sscale[c] + sshift[c];
        }
        __syncthreads();
        #pragma unroll
        for (int it = 0; it < 16; ++it) {
            int idx = it * 256 + tid;
            int pix = idx >> 6;
            int cl  = idx & 63;
            size_t dst;
            if (window_mode) {
                dst = ((size_t)bx * 64 + pix) * CDIM + cc + cl;
            } else {
                int i = pix >> 3, j = pix & 7;
                size_t p = ((size_t)b * HWDIM + h0 + i) * HWDIM + w0 + j;
                dst = p * CDIM + cc + cl;
            }
            out[dst] = __float2half(tile[cl][pix]);
        }
        __syncthreads();
    }
}

// =====================================================================
// fp16 WMMA GEMM, 2-stage cp.async, 3 CTAs/SM.
// Block 128x128x64, 4 warps (2m x 2n), warp tile 64x64.
// EPI: 0 bias->half; 1 bias+GELU->half;
//      2 bias + half-res(NCHW) -> NCHW f32 out (fc2, final);
//      3 bias + window-reverse + f32 x residual -> NCHW HALF (proj -> x1).
// =====================================================================
#define GBM 128
#define GBN 128
#define GBK 64
#define NST 2
#define A_LD 72
#define A_ST_BYTES (GBM * A_LD * 2)          // 18432
#define B_ST_BYTES 18432
#define B_LD_ROW 136
#define STG_BYTES (A_ST_BYTES + B_ST_BYTES)  // 36864
#define GEMM_SMEM (NST * STG_BYTES)          // 73728
#define STG_LD 132
#define NTHR 128

__device__ __forceinline__ void cp_async16(void* dst, const void* src) {
    unsigned int d = (unsigned int)__cvta_generic_to_shared(dst);
    asm volatile("cp.async.cg.shared.global [%0], [%1], 16;\n" :: "r"(d), "l"(src));
}
__device__ __forceinline__ void cp_commit() { asm volatile("cp.async.commit_group;\n"); }
template<int W> __device__ __forceinline__ void cp_wait() {
    asm volatile("cp.async.wait_group %0;\n" :: "n"(W));
}

template<bool B_COL, int EPI>
__global__ __launch_bounds__(NTHR, 3)
void gemm_h(const __half* __restrict__ A, const __half* __restrict__ Bm,
            const float* __restrict__ bias, void* __restrict__ Cv,
            const void* __restrict__ res, int M, int N, int K)
{
    extern __shared__ __align__(16) unsigned char smem[];

    int tid  = threadIdx.x;
    int warp = tid >> 5;
    int wm   = warp >> 1;          // 0..1
    int wn   = warp & 1;           // 0..1
    int n0   = blockIdx.x * GBN;
    int m0   = blockIdx.y * GBM;

    wmma::fragment<wmma::accumulator, 16, 16, 16, float> acc[4][4];
    #pragma unroll
    for (int i = 0; i < 4; ++i)
        #pragma unroll
        for (int j = 0; j < 4; ++j)
            wmma::fill_fragment(acc[i][j], 0.0f);

    const int ktiles = K / GBK;

    auto load_tile = [&](int kt, int s) {
        int k0 = kt * GBK;
        __half* As = (__half*)(smem + s * STG_BYTES);
        __half* Bs = (__half*)(smem + s * STG_BYTES + A_ST_BYTES);
        #pragma unroll
        for (int it = 0; it < 8; ++it) {
            int idx = it * NTHR + tid;
            int r = idx >> 3, c8 = idx & 7;
            cp_async16(As + r * A_LD + c8 * 8, A + (size_t)(m0 + r) * K + k0 + c8 * 8);
        }
        if (B_COL) {
            #pragma unroll
            for (int it = 0; it < 8; ++it) {
                int idx = it * NTHR + tid;
                int r = idx >> 3, c8 = idx & 7;
                cp_async16(Bs + r * A_LD + c8 * 8, Bm + (size_t)(n0 + r) * K + k0 + c8 * 8);
            }
        } else {
            #pragma unroll
            for (int it = 0; it < 8; ++it) {
                int idx = it * NTHR + tid;
                int r = idx >> 4, c8 = idx & 15;
                cp_async16(Bs + r * B_LD_ROW + c8 * 8, Bm + (size_t)(k0 + r) * N + n0 + c8 * 8);
            }
        }
        cp_commit();
    };

    load_tile(0, 0);

    for (int t = 0; t < ktiles; ++t) {
        cp_wait<0>();               // stage t loaded
        __syncthreads();            // other stage fully consumed by all warps
        if (t + 1 < ktiles) load_tile(t + 1, (t + 1) & 1);

        int s = t & 1;
        const __half* As = (const __half*)(smem + s * STG_BYTES);
        const __half* Bs = (const __half*)(smem + s * STG_BYTES + A_ST_BYTES);

        #pragma unroll
        for (int kk = 0; kk < 4; ++kk) {
            wmma::fragment<wmma::matrix_a, 16, 16, 16, __half, wmma::row_major> af[4];
            #pragma unroll
            for (int i = 0; i < 4; ++i)
                wmma::load_matrix_sync(af[i], As + (wm * 64 + i * 16) * A_LD + kk * 16, A_LD);
            #pragma unroll
            for (int j = 0; j < 4; ++j) {
                if (B_COL) {
                    wmma::fragment<wmma::matrix_b, 16, 16, 16, __half, wmma::col_major> bf;
                    wmma::load_matrix_sync(bf, Bs + (wn * 64 + j * 16) * A_LD + kk * 16, A_LD);
                    #pragma unroll
                    for (int i = 0; i < 4; ++i)
                        wmma::mma_sync(acc[i][j], af[i], bf, acc[i][j]);
                } else {
                    wmma::fragment<wmma::matrix_b, 16, 16, 16, __half, wmma::row_major> bf;
                    wmma::load_matrix_sync(bf, Bs + (kk * 16) * B_LD_ROW + wn * 64 + j * 16, B_LD_ROW);
                    #pragma unroll
                    for (int i = 0; i < 4; ++i)
                        wmma::mma_sync(acc[i][j], af[i], bf, acc[i][j]);
                }
            }
        }
    }
    __syncthreads();

    // ---------------- epilogue: staging 128x128 f32 ----------------
    float* stg = (float*)smem;        // [128][STG_LD] = 67584 B
    #pragma unroll
    for (int i = 0; i < 4; ++i)
        #pragma unroll
        for (int j = 0; j < 4; ++j)
            wmma::store_matrix_sync(stg + (size_t)(wm * 64 + i * 16) * STG_LD + wn * 64 + j * 16,
                                    acc[i][j], STG_LD, wmma::mem_row_major);
    __syncthreads();

    #pragma unroll
    for (int it = 0; it < 16; ++it) {
        int e = it * (NTHR * 8) + tid * 8;        // 0..16383
        if (EPI == 2) {
            // final: out = gemm + bias + half residual, NCHW f32
            int r = e & 127, col = e >> 7;        // r 8-consecutive
            int n = n0 + col;
            float bv = bias[n];
            int m = m0 + r;
            int bb = m >> 14, hw = m & 16383;
            size_t oi = ((size_t)bb * CDIM + n) * 16384 + hw;
            const __half* rh = (const __half*)res;
            uint4 rr = *(const uint4*)(rh + oi);
            const __half2* hp = (const __half2*)&rr;
            float2 f0 = __half22float2(hp[0]);
            float2 f1 = __half22float2(hp[1]);
            float2 f2 = __half22float2(hp[2]);
            float2 f3 = __half22float2(hp[3]);
            float4 o0, o1;
            o0.x = stg[(r+0)*STG_LD+col] + bv + f0.x;
            o0.y = stg[(r+1)*STG_LD+col] + bv + f0.y;
            o0.z = stg[(r+2)*STG_LD+col] + bv + f1.x;
            o0.w = stg[(r+3)*STG_LD+col] + bv + f1.y;
            o1.x = stg[(r+4)*STG_LD+col] + bv + f2.x;
            o1.y = stg[(r+5)*STG_LD+col] + bv + f2.y;
            o1.z = stg[(r+6)*STG_LD+col] + bv + f3.x;
            o1.w = stg[(r+7)*STG_LD+col] + bv + f3.y;
            *(float4*)((float*)Cv + oi)     = o0;
            *(float4*)((float*)Cv + oi + 4) = o1;
        } else {
            int col = e & 127, r = e >> 7;        // col 8-aligned consecutive
            int m = m0 + r;
            int n = n0 + col;
            float v[8];
            #pragma unroll
            for (int j = 0; j < 8; ++j) {
                v[j] = stg[r * STG_LD + col + j] + bias[n + j];
                if (EPI == 1)
                    v[j] = 0.5f * v[j] * (1.0f + erff(v[j] * 0.70710678118654752f));
            }
            if (EPI == 3) {
                // proj -> x1 (HALF NCHW): invert torch-view window reverse.
                int bb  = m >> 14;
                int wl  = (m >> 6) & 255;
                int pix = m & 63;
                int q = wl * 32768 + pix * 512 + n;
                size_t base = (size_t)bb * 8388608 + (size_t)(q >> 14) * 16384
                            + (((q >> 10) & 15) * 8 + ((q >> 3) & 7)) * 128
                            + ((q >> 6) & 15) * 8;
                const float* rf = (const float*)res;
                const float4 x0 = *(const float4*)(rf + base);
                const float4 x1v = *(const float4*)(rf + base + 4);
                uint4 pk; __half2 hh;
                hh = __floats2half2_rn(v[0]+x0.x,  v[1]+x0.y);  pk.x = *(unsigned*)&hh;
                hh = __floats2half2_rn(v[2]+x0.z,  v[3]+x0.w);  pk.y = *(unsigned*)&hh;
                hh = __floats2half2_rn(v[4]+x1v.x, v[5]+x1v.y); pk.z = *(unsigned*)&hh;
                hh = __floats2half2_rn(v[6]+x1v.z, v[7]+x1v.w); pk.w = *(unsigned*)&hh;
                *(uint4*)((__half*)Cv + base) = pk;
            } else {
                uint4 pk; __half2 hh;
                hh = __floats2half2_rn(v[0], v[1]); pk.x = *(unsigned*)&hh;
                hh = __floats2half2_rn(v[2], v[3]); pk.y = *(unsigned*)&hh;
                hh = __floats2half2_rn(v[4], v[5]); pk.z = *(unsigned*)&hh;
                hh = __floats2half2_rn(v[6], v[7]); pk.w = *(unsigned*)&hh;
                *(uint4*)((__half*)Cv + (size_t)m * N + n) = pk;
            }
        }
    }
}

// =====================================================================
// tensor-core attention: one block per (window, head), 64 threads (2 warps).
// =====================================================================
#define QK_LD 40    // halfs
#define S_LD  68    // floats
#define P_LD  72    // halfs

__global__ __launch_bounds__(64)
void attn_tc_kernel(const __half* __restrict__ qkv, const float* __restrict__ bias16,
                    __half* __restrict__ ctx)
{
    __shared__ __align__(16) __half Qs[64 * QK_LD];
    __shared__ __align__(16) __half Ks[64 * QK_LD];
    __shared__ __align__(16) __half Vs[64 * QK_LD];
    __shared__ __align__(16) float  Ss[64 * S_LD];
    __shared__ __align__(16) __half Ps[64 * P_LD];

    int win  = blockIdx.x >> 4;
    int head = blockIdx.x & 15;
    int tid  = threadIdx.x;
    int warp = tid >> 5;

    size_t base = (size_t)win * 64 * QKVN + head * 32;
    #pragma unroll
    for (int i = 0; i < 4; ++i) {
        int idx = i * 64 + tid;
        int tok = idx >> 2, c = idx & 3;
        size_t off = base + (size_t)tok * QKVN + c * 8;
        *(uint4*)(Qs + tok * QK_LD + c * 8) = *(const uint4*)(qkv + off);
        *(uint4*)(Ks + tok * QK_LD + c * 8) = *(const uint4*)(qkv + off + 512);
        *(uint4*)(Vs + tok * QK_LD + c * 8) = *(const uint4*)(qkv + off + 1024);
    }
    __syncthreads();

    {
        wmma::fragment<wmma::accumulator, 16, 16, 16, float> sacc[2][4];
        #pragma unroll
        for (int i = 0; i < 2; ++i)
            #pragma unroll
            for (int j = 0; j < 4; ++j)
                wmma::fill_fragment(sacc[i][j], 0.0f);
        #pragma unroll
        for (int kk = 0; kk < 32; kk += 16) {
            wmma::fragment<wmma::matrix_a, 16, 16, 16, __half, wmma::row_major> af[2];
            wmma::fragment<wmma::matrix_b, 16, 16, 16, __half, wmma::col_major> bf[4];
            #pragma unroll
            for (int i = 0; i < 2; ++i)
                wmma::load_matrix_sync(af[i], Qs + (warp * 32 + i * 16) * QK_LD + kk, QK_LD);
            #pragma unroll
            for (int j = 0; j < 4; ++j)
                wmma::load_matrix_sync(bf[j], Ks + (j * 16) * QK_LD + kk, QK_LD);
            #pragma unroll
            for (int i = 0; i < 2; ++i)
                #pragma unroll
                for (int j = 0; j < 4; ++j)
                    wmma::mma_sync(sacc[i][j], af[i], bf[j], sacc[i][j]);
        }
        #pragma unroll
        for (int i = 0; i < 2; ++i)
            #pragma unroll
            for (int j = 0; j < 4; ++j)
                wmma::store_matrix_sync(Ss + (warp * 32 + i * 16) * S_LD + j * 16,
                                        sacc[i][j], S_LD, wmma::mem_row_major);
    }
    __syncthreads();

    {
        int r = tid;
        const float* brow = bias16 + ((size_t)head * 64 + r) * 64;
        float v[64];
        float mx = -1e30f;
        #pragma unroll
        for (int q = 0; q < 16; ++q) {
            float4 s = *(float4*)(Ss + r * S_LD + q * 4);
            float4 b = *(const float4*)(brow + q * 4);
            v[q*4+0] = s.x * ATTN_SCALE + b.x;
            v[q*4+1] = s.y * ATTN_SCALE + b.y;
            v[q*4+2] = s.z * ATTN_SCALE + b.z;
            v[q*4+3] = s.w * ATTN_SCALE + b.w;
            mx = fmaxf(mx, fmaxf(fmaxf(v[q*4+0], v[q*4+1]), fmaxf(v[q*4+2], v[q*4+3])));
        }
        float sum = 0.0f;
        #pragma unroll
        for (int m = 0; m < 64; ++m) { v[m] = __expf(v[m] - mx); sum += v[m]; }
        float inv = 1.0f / sum;
        #pragma unroll
        for (int q = 0; q < 8; ++q) {
            uint4 pk; __half2 hh;
            hh = __floats2half2_rn(v[q*8+0]*inv, v[q*8+1]*inv); pk.x = *(unsigned*)&hh;
            hh = __floats2half2_rn(v[q*8+2]*inv, v[q*8+3]*inv); pk.y = *(unsigned*)&hh;
            hh = __floats2half2_rn(v[q*8+4]*inv, v[q*8+5]*inv); pk.z = *(unsigned*)&hh;
            hh = __floats2half2_rn(v[q*8+6]*inv, v[q*8+7]*inv); pk.w = *(unsigned*)&hh;
            *(uint4*)(Ps + r * P_LD + q * 8) = pk;
        }
    }
    __syncthreads();

    {
        wmma::fragment<wmma::accumulator, 16, 16, 16, float> oacc[2][2];
        #pragma unroll
        for (int i = 0; i < 2; ++i)
            #pragma unroll
            for (int j = 0; j < 2; ++j)
                wmma::fill_fragment(oacc[i][j], 0.0f);
        #pragma unroll
        for (int kk = 0; kk < 64; kk += 16) {
            wmma::fragment<wmma::matrix_a, 16, 16, 16, __half, wmma::row_major> af[2];
            wmma::fragment<wmma::matrix_b, 16, 16, 16, __half, wmma::row_major> bf[2];
            #pragma unroll
            for (int i = 0; i < 2; ++i)
                wmma::load_matrix_sync(af[i], Ps + (warp * 32 + i * 16) * P_LD + kk, P_LD);
            #pragma unroll
            for (int j = 0; j < 2; ++j)
                wmma::load_matrix_sync(bf[j], Vs + kk * QK_LD + j * 16, QK_LD);
            #pragma unroll
            for (int i = 0; i < 2; ++i)
                #pragma unroll
                for (int j = 0; j < 2; ++j)
                    wmma::mma_sync(oacc[i][j], af[i], bf[j], oacc[i][j]);
        }
        #pragma unroll
        for (int i = 0; i < 2; ++i)
            #pragma unroll
            for (int j = 0; j < 2; ++j)
                wmma::store_matrix_sync(Ss + (warp * 32 + i * 16) * S_LD + j * 16,
                                        oacc[i][j], S_LD, wmma::mem_row_major);
    }
    __syncthreads();

    {
        int r = tid;
        size_t ob = ((size_t)win * 64 + r) * CDIM + head * 32;
        #pragma unroll
        for (int q = 0; q < 4; ++q) {
            float4 a = *(float4*)(Ss + r * S_LD + q * 8);
            float4 b = *(float4*)(Ss + r * S_LD + q * 8 + 4);
            uint4 pk; __half2 hh;
            hh = __floats2half2_rn(a.x, a.y); pk.x = *(unsigned*)&hh;
            hh = __floats2half2_rn(a.z, a.w); pk.y = *(unsigned*)&hh;
            hh = __floats2half2_rn(b.x, b.y); pk.z = *(unsigned*)&hh;
            hh = __floats2half2_rn(b.z, b.w); pk.w = *(unsigned*)&hh;
            *(uint4*)(ctx + ob + q * 8) = pk;
        }
    }
}

// =====================================================================
extern "C" void kernel_launch(void* const* d_in, const int* in_sizes, int n_in,
                              void* d_out, int out_size)
{
    const float* x      = (const float*)d_in[0];
    const float* qkv_w  = (const float*)d_in[1];
    const float* qkv_b  = (const float*)d_in[2];
    const float* proj_w = (const float*)d_in[3];
    const float* proj_b = (const float*)d_in[4];
    const float* relt   = (const float*)d_in[5];
    const float* bn1g   = (const float*)d_in[6];
    const float* bn1b   = (const float*)d_in[7];
    const float* bn1m   = (const float*)d_in[8];
    const float* bn1v   = (const float*)d_in[9];
    const float* mlp_w1 = (const float*)d_in[10];
    const float* mlp_b1 = (const float*)d_in[11];
    const float* mlp_w2 = (const float*)d_in[12];
    const float* mlp_b2 = (const float*)d_in[13];
    const float* bn2g   = (const float*)d_in[14];
    const float* bn2b   = (const float*)d_in[15];
    const float* bn2m   = (const float*)d_in[16];
    const float* bn2v   = (const float*)d_in[17];
    float* out = (float*)d_out;

    __half *p_xw, *p_qkv, *p_ctx, *p_x1, *p_xn2, *p_h, *p_wqkv, *p_wproj, *p_w1, *p_w2;
    float  *p_bias;
    cudaGetSymbolAddress((void**)&p_xw,   g_xw);
    cudaGetSymbolAddress((void**)&p_qkv,  g_qkv);
    cudaGetSymbolAddress((void**)&p_ctx,  g_ctx);
    cudaGetSymbolAddress((void**)&p_x1,   g_x1);
    cudaGetSymbolAddress((void**)&p_xn2,  g_xn2);
    cudaGetSymbolAddress((void**)&p_h,    g_h);
    cudaGetSymbolAddress((void**)&p_wqkv, g_wqkv);
    cudaGetSymbolAddress((void**)&p_wproj,g_wproj);
    cudaGetSymbolAddress((void**)&p_w1,   g_w1);
    cudaGetSymbolAddress((void**)&p_w2,   g_w2);
    cudaGetSymbolAddress((void**)&p_bias, g_bias);

    cudaFuncSetAttribute(gemm_h<false, 0>, cudaFuncAttributeMaxDynamicSharedMemorySize, GEMM_SMEM);
    cudaFuncSetAttribute(gemm_h<false, 3>, cudaFuncAttributeMaxDynamicSharedMemorySize, GEMM_SMEM);
    cudaFuncSetAttribute(gemm_h<true, 1>,  cudaFuncAttributeMaxDynamicSharedMemorySize, GEMM_SMEM);
    cudaFuncSetAttribute(gemm_h<true, 2>,  cudaFuncAttributeMaxDynamicSharedMemorySize, GEMM_SMEM);

    // 0) weight conversions (batched) + bias expansion
    cvt_all_kernel<<<1536, 256>>>(qkv_w, proj_w, mlp_w1, mlp_w2,
                                  p_wqkv, p_wproj, p_w1, p_w2);
    bias_expand_kernel<<<256, 256>>>(relt, p_bias);

    // 1) BN1 + window partition
    prep_kernel<<<NWIN, 256>>>(x, bn1g, bn1b, bn1m, bn1v, p_xw, 1);

    // 2) QKV projection
    gemm_h<false, 0><<<dim3(QKVN / GBN, MTOT / GBM), NTHR, GEMM_SMEM>>>(
        p_xw, p_wqkv, qkv_b, p_qkv, nullptr, MTOT, QKVN, CDIM);

    // 3) windowed attention (tensor cores)
    attn_tc_kernel<<<NWIN * 16, 64>>>(p_qkv, p_bias, p_ctx);

    // 4) proj + window-reverse + x residual -> x1 (NCHW half), fused
    gemm_h<false, 3><<<dim3(CDIM / GBN, MTOT / GBM), NTHR, GEMM_SMEM>>>(
        p_ctx, p_wproj, proj_b, p_x1, x, MTOT, CDIM, CDIM);

    // 5) BN2 + pixel-major transpose (half input)
    prep_kernel<<<NWIN, 256>>>(p_x1, bn2g, bn2b, bn2m, bn2v, p_xn2, 0);

    // 6) FC1 + GELU
    gemm_h<true, 1><<<dim3(CDIM / GBN, MTOT / GBM), NTHR, GEMM_SMEM>>>(
        p_xn2, p_w1, mlp_b1, p_h, nullptr, MTOT, CDIM, CDIM);

    // 7) FC2 + bias + half residual -> NCHW f32 output
    gemm_h<true, 2><<<dim3(CDIM / GBN, MTOT / GBM), NTHR, GEMM_SMEM>>>(
        p_h, p_w2, mlp_b2, out, p_x1, MTOT, CDIM, CDIM);
}

// round 11
// speedup vs baseline: 1.2422x; 1.1388x over previous
#include <cuda_runtime.h>
#include <cuda_fp16.h>
#include <mma.h>
#include <cstdint>

using namespace nvcuda;

// ---------------- problem constants ----------------
#define BATCH   8
#define CDIM    512
#define HWDIM   128
#define NWIN    2048
#define MTOT    131072
#define QKVN    1536
#define ATTN_SCALE 0.17677669529663687f   // 32^-0.5
#define AUXBLK  1792                      // cvt (1536) + bias (256) aux blocks

// ---------------- scratch (device globals; no runtime alloc) ----------------
__device__ __half g_xw  [(size_t)MTOT * CDIM];
__device__ __half g_qkv [(size_t)MTOT * QKVN];
__device__ __half g_ctx [(size_t)MTOT * CDIM];
__device__ float  g_x1  [(size_t)MTOT * CDIM];   // NCHW f32
__device__ __half g_xn2 [(size_t)MTOT * CDIM];
__device__ __half g_h   [(size_t)MTOT * CDIM];
__device__ __half g_wqkv [CDIM * QKVN];   // [K,N]
__device__ __half g_wproj[CDIM * CDIM];   // [K,N]
__device__ __half g_w1   [CDIM * CDIM];   // [o,c] = [N,K]
__device__ __half g_w2   [CDIM * CDIM];
__device__ float  g_bias [16 * 64 * 64];  // expanded rel-pos bias [head][n][m]

// =====================================================================
// prep: BN + layout transform -> half; aux blocks do weight-cvt + bias expand.
// window_mode=1: out[(win*64+pix)*512 + c]; 0: out[pixel*512 + c]
// =====================================================================
__global__ __launch_bounds__(256)
void prep_kernel(const float* __restrict__ in,
                 const float* __restrict__ gamma, const float* __restrict__ beta,
                 const float* __restrict__ mean,  const float* __restrict__ var,
                 __half* __restrict__ out, int window_mode,
                 const float* __restrict__ w0, const float* __restrict__ w1,
                 const float* __restrict__ w2, const float* __restrict__ w3,
                 __half* __restrict__ o0, __half* __restrict__ o1,
                 __half* __restrict__ o2, __half* __restrict__ o3,
                 const float* __restrict__ relt, float* __restrict__ biasx)
{
    __shared__ float sscale[CDIM];
    __shared__ float sshift[CDIM];
    __shared__ float tile[64][65];

    int bx  = blockIdx.x;
    int tid = threadIdx.x;

    if (bx >= NWIN) {
        // aux work: weight f32->f16 conversions, then bias expand
        int i = (bx - NWIN) * 256 + tid;            // 0 .. 458751
        if (i < 393216) {
            const float* ip; __half* op; int idx;
            if (i < 196608)      { ip = w0; op = o0; idx = i; }
            else if (i < 262144) { ip = w1; op = o1; idx = i - 196608; }
            else if (i < 327680) { ip = w2; op = o2; idx = i - 262144; }
            else                 { ip = w3; op = o3; idx = i - 327680; }
            float4 v = ((const float4*)ip)[idx];
            __half2* o = (__half2*)op + idx * 2;
            o[0] = __floats2half2_rn(v.x, v.y);
            o[1] = __floats2half2_rn(v.z, v.w);
        } else {
            int idx = i - 393216;                    // 0..65535
            int m = idx & 63;
            int n = (idx >> 6) & 63;
            int h = idx >> 12;
            int i1 = n >> 3, j1 = n & 7;
            int i2 = m >> 3, j2 = m & 7;
            int ridx = (i1 - i2 + 7) * 15 + (j1 - j2 + 7);
            biasx[idx] = relt[ridx * 16 + h];
        }
        return;
    }

    int b   = bx >> 8;
    int hb  = (bx >> 4) & 15;
    int wb  = bx & 15;

    for (int c = tid; c < CDIM; c += 256) {
        float inv = rsqrtf(var[c] + 1e-5f);
        float sc  = gamma[c] * inv;
        sscale[c] = sc;
        sshift[c] = beta[c] - mean[c] * sc;
    }
    __syncthreads();

    int h0 = hb * 8, w0p = wb * 8;
    for (int cc = 0; cc < CDIM; cc += 64) {
        #pragma unroll
        for (int it = 0; it < 16; ++it) {
            int idx = it * 256 + tid;
            int cl  = idx >> 6;
            int pix = idx & 63;
            int c   = cc + cl;
            int i   = pix >> 3, j = pix & 7;
            float v = in[(((size_t)b * CDIM + c) * HWDIM + h0 + i) * HWDIM + w0p + j];
            tile[cl][pix] = v * sscale[c] + sshift[c];
        }
        __syncthreads();
        #pragma unroll
        for (int it = 0; it < 16; ++it) {
            int idx = it * 256 + tid;
            int pix = idx >> 6;
            int cl  = idx & 63;
            size_t dst;
            if (window_mode) {
                dst = ((size_t)bx * 64 + pix) * CDIM + cc + cl;
            } else {
                int i = pix >> 3, j = pix & 7;
                size_t p = ((size_t)b * HWDIM + h0 + i) * HWDIM + w0p + j;
                dst = p * CDIM + cc + cl;
            }
            out[dst] = __float2half(tile[cl][pix]);
        }
        __syncthreads();
    }
}

// =====================================================================
// fp16 WMMA GEMM, 2-stage cp.async, 3 CTAs/SM.  (round-8 config)
// Block 128x128x64, 4 warps (2m x 2n), warp tile 64x64.
// EPI: 0 bias->half; 1 bias+GELU->half; 2 bias+f32 res->NCHW f32;
//      3 bias + window-reverse + x residual -> NCHW f32 (proj -> x1).
// =====================================================================
#define GBM 128
#define GBN 128
#define GBK 64
#define NST 2
#define A_LD 72
#define A_ST_BYTES (GBM * A_LD * 2)          // 18432
#define B_ST_BYTES 18432
#define B_LD_ROW 136
#define STG_BYTES (A_ST_BYTES + B_ST_BYTES)  // 36864
#define GEMM_SMEM (NST * STG_BYTES)          // 73728
#define STG_LD 132
#define NTHR 128

__device__ __forceinline__ void cp_async16(void* dst, const void* src) {
    unsigned int d = (unsigned int)__cvta_generic_to_shared(dst);
    asm volatile("cp.async.cg.shared.global [%0], [%1], 16;\n" :: "r"(d), "l"(src));
}
__device__ __forceinline__ void cp_commit() { asm volatile("cp.async.commit_group;\n"); }
template<int W> __device__ __forceinline__ void cp_wait() {
    asm volatile("cp.async.wait_group %0;\n" :: "n"(W));
}

template<bool B_COL, int EPI>
__global__ __launch_bounds__(NTHR, 3)
void gemm_h(const __half* __restrict__ A, const __half* __restrict__ Bm,
            const float* __restrict__ bias, void* __restrict__ Cv,
            const float* __restrict__ res, int M, int N, int K)
{
    extern __shared__ __align__(16) unsigned char smem[];

    int tid  = threadIdx.x;
    int warp = tid >> 5;
    int wm   = warp >> 1;          // 0..1
    int wn   = warp & 1;           // 0..1
    int n0   = blockIdx.x * GBN;
    int m0   = blockIdx.y * GBM;

    wmma::fragment<wmma::accumulator, 16, 16, 16, float> acc[4][4];
    #pragma unroll
    for (int i = 0; i < 4; ++i)
        #pragma unroll
        for (int j = 0; j < 4; ++j)
            wmma::fill_fragment(acc[i][j], 0.0f);

    const int ktiles = K / GBK;

    auto load_tile = [&](int kt, int s) {
        int k0 = kt * GBK;
        __half* As = (__half*)(smem + s * STG_BYTES);
        __half* Bs = (__half*)(smem + s * STG_BYTES + A_ST_BYTES);
        #pragma unroll
        for (int it = 0; it < 8; ++it) {
            int idx = it * NTHR + tid;
            int r = idx >> 3, c8 = idx & 7;
            cp_async16(As + r * A_LD + c8 * 8, A + (size_t)(m0 + r) * K + k0 + c8 * 8);
        }
        if (B_COL) {
            #pragma unroll
            for (int it = 0; it < 8; ++it) {
                int idx = it * NTHR + tid;
                int r = idx >> 3, c8 = idx & 7;
                cp_async16(Bs + r * A_LD + c8 * 8, Bm + (size_t)(n0 + r) * K + k0 + c8 * 8);
            }
        } else {
            #pragma unroll
            for (int it = 0; it < 8; ++it) {
                int idx = it * NTHR + tid;
                int r = idx >> 4, c8 = idx & 15;
                cp_async16(Bs + r * B_LD_ROW + c8 * 8, Bm + (size_t)(k0 + r) * N + n0 + c8 * 8);
            }
        }
        cp_commit();
    };

    load_tile(0, 0);

    for (int t = 0; t < ktiles; ++t) {
        cp_wait<0>();               // stage t loaded
        __syncthreads();            // other stage fully consumed by all warps
        if (t + 1 < ktiles) load_tile(t + 1, (t + 1) & 1);

        int s = t & 1;
        const __half* As = (const __half*)(smem + s * STG_BYTES);
        const __half* Bs = (const __half*)(smem + s * STG_BYTES + A_ST_BYTES);

        #pragma unroll
        for (int kk = 0; kk < 4; ++kk) {
            wmma::fragment<wmma::matrix_a, 16, 16, 16, __half, wmma::row_major> af[4];
            #pragma unroll
            for (int i = 0; i < 4; ++i)
                wmma::load_matrix_sync(af[i], As + (wm * 64 + i * 16) * A_LD + kk * 16, A_LD);
            #pragma unroll
            for (int j = 0; j < 4; ++j) {
                if (B_COL) {
                    wmma::fragment<wmma::matrix_b, 16, 16, 16, __half, wmma::col_major> bf;
                    wmma::load_matrix_sync(bf, Bs + (wn * 64 + j * 16) * A_LD + kk * 16, A_LD);
                    #pragma unroll
                    for (int i = 0; i < 4; ++i)
                        wmma::mma_sync(acc[i][j], af[i], bf, acc[i][j]);
                } else {
                    wmma::fragment<wmma::matrix_b, 16, 16, 16, __half, wmma::row_major> bf;
                    wmma::load_matrix_sync(bf, Bs + (kk * 16) * B_LD_ROW + wn * 64 + j * 16, B_LD_ROW);
                    #pragma unroll
                    for (int i = 0; i < 4; ++i)
                        wmma::mma_sync(acc[i][j], af[i], bf, acc[i][j]);
                }
            }
        }
    }
    __syncthreads();

    // ---------------- epilogue: staging 128x128 f32 ----------------
    float* stg = (float*)smem;        // [128][STG_LD] = 67584 B
    #pragma unroll
    for (int i = 0; i < 4; ++i)
        #pragma unroll
        for (int j = 0; j < 4; ++j)
            wmma::store_matrix_sync(stg + (size_t)(wm * 64 + i * 16) * STG_LD + wn * 64 + j * 16,
                                    acc[i][j], STG_LD, wmma::mem_row_major);
    __syncthreads();

    #pragma unroll
    for (int it = 0; it < 16; ++it) {
        int e = it * (NTHR * 8) + tid * 8;        // 0..16383
        if (EPI == 2) {
            int r = e & 127, col = e >> 7;        // r 8-consecutive
            int n = n0 + col;
            float bv = bias[n];
            int m = m0 + r;
            int bb = m >> 14, hw = m & 16383;
            size_t oi = ((size_t)bb * CDIM + n) * 16384 + hw;
            float4 o0, o1;
            const float4 r0 = *(const float4*)(res + oi);
            const float4 r1 = *(const float4*)(res + oi + 4);
            o0.x = stg[(r+0)*STG_LD+col] + bv + r0.x;
            o0.y = stg[(r+1)*STG_LD+col] + bv + r0.y;
            o0.z = stg[(r+2)*STG_LD+col] + bv + r0.z;
            o0.w = stg[(r+3)*STG_LD+col] + bv + r0.w;
            o1.x = stg[(r+4)*STG_LD+col] + bv + r1.x;
            o1.y = stg[(r+5)*STG_LD+col] + bv + r1.y;
            o1.z = stg[(r+6)*STG_LD+col] + bv + r1.z;
            o1.w = stg[(r+7)*STG_LD+col] + bv + r1.w;
            *(float4*)((float*)Cv + oi)     = o0;
            *(float4*)((float*)Cv + oi + 4) = o1;
        } else {
            int col = e & 127, r = e >> 7;        // col 8-aligned consecutive
            int m = m0 + r;
            int n = n0 + col;
            float v[8];
            #pragma unroll
            for (int j = 0; j < 8; ++j) {
                v[j] = stg[r * STG_LD + col + j] + bias[n + j];
                if (EPI == 1)
                    v[j] = 0.5f * v[j] * (1.0f + erff(v[j] * 0.70710678118654752f));
            }
            if (EPI == 3) {
                int bb  = m >> 14;
                int wl  = (m >> 6) & 255;
                int pix = m & 63;
                int q = wl * 32768 + pix * 512 + n;
                size_t base = (size_t)bb * 8388608 + (size_t)(q >> 14) * 16384
                            + (((q >> 10) & 15) * 8 + ((q >> 3) & 7)) * 128
                            + ((q >> 6) & 15) * 8;
                const float4 x0 = *(const float4*)(res + base);
                const float4 x1v = *(const float4*)(res + base + 4);
                float4 o0 = make_float4(v[0]+x0.x, v[1]+x0.y, v[2]+x0.z, v[3]+x0.w);
                float4 o1 = make_float4(v[4]+x1v.x, v[5]+x1v.y, v[6]+x1v.z, v[7]+x1v.w);
                *(float4*)((float*)Cv + base)     = o0;
                *(float4*)((float*)Cv + base + 4) = o1;
            } else {
                uint4 pk; __half2 hh;
                hh = __floats2half2_rn(v[0], v[1]); pk.x = *(unsigned*)&hh;
                hh = __floats2half2_rn(v[2], v[3]); pk.y = *(unsigned*)&hh;
                hh = __floats2half2_rn(v[4], v[5]); pk.z = *(unsigned*)&hh;
                hh = __floats2half2_rn(v[6], v[7]); pk.w = *(unsigned*)&hh;
                *(uint4*)((__half*)Cv + (size_t)m * N + n) = pk;
            }
        }
    }
}

// =====================================================================
// tensor-core attention: one block per (window, head), 64 threads (2 warps).
// P matrix aliased into S buffer -> 32KB smem/block (6 blocks/SM).
// =====================================================================
#define QK_LD 40    // halfs
#define S_LD  68    // floats
#define P_LDH (S_LD * 2)   // 136 halfs (P aliased over S)

__global__ __launch_bounds__(64)
void attn_tc_kernel(const __half* __restrict__ qkv, const float* __restrict__ bias16,
                    __half* __restrict__ ctx)
{
    __shared__ __align__(16) __half Qs[64 * QK_LD];
    __shared__ __align__(16) __half Ks[64 * QK_LD];
    __shared__ __align__(16) __half Vs[64 * QK_LD];
    __shared__ __align__(16) float  Ss[64 * S_LD];

    int win  = blockIdx.x >> 4;
    int head = blockIdx.x & 15;
    int tid  = threadIdx.x;
    int warp = tid >> 5;

    size_t base = (size_t)win * 64 * QKVN + head * 32;
    #pragma unroll
    for (int i = 0; i < 4; ++i) {
        int idx = i * 64 + tid;
        int tok = idx >> 2, c = idx & 3;
        size_t off = base + (size_t)tok * QKVN + c * 8;
        *(uint4*)(Qs + tok * QK_LD + c * 8) = *(const uint4*)(qkv + off);
        *(uint4*)(Ks + tok * QK_LD + c * 8) = *(const uint4*)(qkv + off + 512);
        *(uint4*)(Vs + tok * QK_LD + c * 8) = *(const uint4*)(qkv + off + 1024);
    }
    __syncthreads();

    // S = Q @ K^T  (64x64x32)
    {
        wmma::fragment<wmma::accumulator, 16, 16, 16, float> sacc[2][4];
        #pragma unroll
        for (int i = 0; i < 2; ++i)
            #pragma unroll
            for (int j = 0; j < 4; ++j)
                wmma::fill_fragment(sacc[i][j], 0.0f);
        #pragma unroll
        for (int kk = 0; kk < 32; kk += 16) {
            wmma::fragment<wmma::matrix_a, 16, 16, 16, __half, wmma::row_major> af[2];
            wmma::fragment<wmma::matrix_b, 16, 16, 16, __half, wmma::col_major> bf[4];
            #pragma unroll
            for (int i = 0; i < 2; ++i)
                wmma::load_matrix_sync(af[i], Qs + (warp * 32 + i * 16) * QK_LD + kk, QK_LD);
            #pragma unroll
            for (int j = 0; j < 4; ++j)
                wmma::load_matrix_sync(bf[j], Ks + (j * 16) * QK_LD + kk, QK_LD);
            #pragma unroll
            for (int i = 0; i < 2; ++i)
                #pragma unroll
                for (int j = 0; j < 4; ++j)
                    wmma::mma_sync(sacc[i][j], af[i], bf[j], sacc[i][j]);
        }
        #pragma unroll
        for (int i = 0; i < 2; ++i)
            #pragma unroll
            for (int j = 0; j < 4; ++j)
                wmma::store_matrix_sync(Ss + (warp * 32 + i * 16) * S_LD + j * 16,
                                        sacc[i][j], S_LD, wmma::mem_row_major);
    }
    __syncthreads();

    // softmax row r = tid (reads full S row into regs, then writes half P over it)
    {
        int r = tid;
        const float* brow = bias16 + ((size_t)head * 64 + r) * 64;
        float v[64];
        float mx = -1e30f;
        #pragma unroll
        for (int q = 0; q < 16; ++q) {
            float4 s = *(float4*)(Ss + r * S_LD + q * 4);
            float4 b = *(const float4*)(brow + q * 4);
            v[q*4+0] = s.x * ATTN_SCALE + b.x;
            v[q*4+1] = s.y * ATTN_SCALE + b.y;
            v[q*4+2] = s.z * ATTN_SCALE + b.z;
            v[q*4+3] = s.w * ATTN_SCALE + b.w;
            mx = fmaxf(mx, fmaxf(fmaxf(v[q*4+0], v[q*4+1]), fmaxf(v[q*4+2], v[q*4+3])));
        }
        float sum = 0.0f;
        #pragma unroll
        for (int m = 0; m < 64; ++m) { v[m] = __expf(v[m] - mx); sum += v[m]; }
        float inv = 1.0f / sum;
        __half* Ps = (__half*)Ss;
        #pragma unroll
        for (int q = 0; q < 8; ++q) {
            uint4 pk; __half2 hh;
            hh = __floats2half2_rn(v[q*8+0]*inv, v[q*8+1]*inv); pk.x = *(unsigned*)&hh;
            hh = __floats2half2_rn(v[q*8+2]*inv, v[q*8+3]*inv); pk.y = *(unsigned*)&hh;
            hh = __floats2half2_rn(v[q*8+4]*inv, v[q*8+5]*inv); pk.z = *(unsigned*)&hh;
            hh = __floats2half2_rn(v[q*8+6]*inv, v[q*8+7]*inv); pk.w = *(unsigned*)&hh;
            *(uint4*)(Ps + r * P_LDH + q * 8) = pk;
        }
    }
    __syncthreads();

    // O = P @ V  (64x32x64)
    {
        const __half* Ps = (const __half*)Ss;
        wmma::fragment<wmma::accumulator, 16, 16, 16, float> oacc[2][2];
        #pragma unroll
        for (int i = 0; i < 2; ++i)
            #pragma unroll
            for (int j = 0; j < 2; ++j)
                wmma::fill_fragment(oacc[i][j], 0.0f);
        #pragma unroll
        for (int kk = 0; kk < 64; kk += 16) {
            wmma::fragment<wmma::matrix_a, 16, 16, 16, __half, wmma::row_major> af[2];
            wmma::fragment<wmma::matrix_b, 16, 16, 16, __half, wmma::row_major> bf[2];
            #pragma unroll
            for (int i = 0; i < 2; ++i)
                wmma::load_matrix_sync(af[i], Ps + (warp * 32 + i * 16) * P_LDH + kk, P_LDH);
            #pragma unroll
            for (int j = 0; j < 2; ++j)
                wmma::load_matrix_sync(bf[j], Vs + kk * QK_LD + j * 16, QK_LD);
            #pragma unroll
            for (int i = 0; i < 2; ++i)
                #pragma unroll
                for (int j = 0; j < 2; ++j)
                    wmma::mma_sync(oacc[i][j], af[i], bf[j], oacc[i][j]);
        }
        // each warp overwrites only its own 32 S rows, after all its P loads
        #pragma unroll
        for (int i = 0; i < 2; ++i)
            #pragma unroll
            for (int j = 0; j < 2; ++j)
                wmma::store_matrix_sync(Ss + (warp * 32 + i * 16) * S_LD + j * 16,
                                        oacc[i][j], S_LD, wmma::mem_row_major);
    }
    __syncthreads();

    {
        int r = tid;
        size_t ob = ((size_t)win * 64 + r) * CDIM + head * 32;
        #pragma unroll
        for (int q = 0; q < 4; ++q) {
            float4 a = *(float4*)(Ss + r * S_LD + q * 8);
            float4 b = *(float4*)(Ss + r * S_LD + q * 8 + 4);
            uint4 pk; __half2 hh;
            hh = __floats2half2_rn(a.x, a.y); pk.x = *(unsigned*)&hh;
            hh = __floats2half2_rn(a.z, a.w); pk.y = *(unsigned*)&hh;
            hh = __floats2half2_rn(b.x, b.y); pk.z = *(unsigned*)&hh;
            hh = __floats2half2_rn(b.z, b.w); pk.w = *(unsigned*)&hh;
            *(uint4*)(ctx + ob + q * 8) = pk;
        }
    }
}

// =====================================================================
extern "C" void kernel_launch(void* const* d_in, const int* in_sizes, int n_in,
                              void* d_out, int out_size)
{
    const float* x      = (const float*)d_in[0];
    const float* qkv_w  = (const float*)d_in[1];
    const float* qkv_b  = (const float*)d_in[2];
    const float* proj_w = (const float*)d_in[3];
    const float* proj_b = (const float*)d_in[4];
    const float* relt   = (const float*)d_in[5];
    const float* bn1g   = (const float*)d_in[6];
    const float* bn1b   = (const float*)d_in[7];
    const float* bn1m   = (const float*)d_in[8];
    const float* bn1v   = (const float*)d_in[9];
    const float* mlp_w1 = (const float*)d_in[10];
    const float* mlp_b1 = (const float*)d_in[11];
    const float* mlp_w2 = (const float*)d_in[12];
    const float* mlp_b2 = (const float*)d_in[13];
    const float* bn2g   = (const float*)d_in[14];
    const float* bn2b   = (const float*)d_in[15];
    const float* bn2m   = (const float*)d_in[16];
    const float* bn2v   = (const float*)d_in[17];
    float* out = (float*)d_out;

    __half *p_xw, *p_qkv, *p_ctx, *p_xn2, *p_h, *p_wqkv, *p_wproj, *p_w1, *p_w2;
    float  *p_x1, *p_bias;
    cudaGetSymbolAddress((void**)&p_xw,   g_xw);
    cudaGetSymbolAddress((void**)&p_qkv,  g_qkv);
    cudaGetSymbolAddress((void**)&p_ctx,  g_ctx);
    cudaGetSymbolAddress((void**)&p_x1,   g_x1);
    cudaGetSymbolAddress((void**)&p_xn2,  g_xn2);
    cudaGetSymbolAddress((void**)&p_h,    g_h);
    cudaGetSymbolAddress((void**)&p_wqkv, g_wqkv);
    cudaGetSymbolAddress((void**)&p_wproj,g_wproj);
    cudaGetSymbolAddress((void**)&p_w1,   g_w1);
    cudaGetSymbolAddress((void**)&p_w2,   g_w2);
    cudaGetSymbolAddress((void**)&p_bias, g_bias);

    cudaFuncSetAttribute(gemm_h<false, 0>, cudaFuncAttributeMaxDynamicSharedMemorySize, GEMM_SMEM);
    cudaFuncSetAttribute(gemm_h<false, 3>, cudaFuncAttributeMaxDynamicSharedMemorySize, GEMM_SMEM);
    cudaFuncSetAttribute(gemm_h<true, 1>,  cudaFuncAttributeMaxDynamicSharedMemorySize, GEMM_SMEM);
    cudaFuncSetAttribute(gemm_h<true, 2>,  cudaFuncAttributeMaxDynamicSharedMemorySize, GEMM_SMEM);

    // 1) BN1 + window partition, with fused weight-cvt + bias-expand aux blocks
    prep_kernel<<<NWIN + AUXBLK, 256>>>(x, bn1g, bn1b, bn1m, bn1v, p_xw, 1,
                                        qkv_w, proj_w, mlp_w1, mlp_w2,
                                        p_wqkv, p_wproj, p_w1, p_w2,
                                        relt, p_bias);

    // 2) QKV projection
    gemm_h<false, 0><<<dim3(QKVN / GBN, MTOT / GBM), NTHR, GEMM_SMEM>>>(
        p_xw, p_wqkv, qkv_b, p_qkv, nullptr, MTOT, QKVN, CDIM);

    // 3) windowed attention (tensor cores)
    attn_tc_kernel<<<NWIN * 16, 64>>>(p_qkv, p_bias, p_ctx);

    // 4) proj + window-reverse + x residual -> x1 (NCHW f32), fused
    gemm_h<false, 3><<<dim3(CDIM / GBN, MTOT / GBM), NTHR, GEMM_SMEM>>>(
        p_ctx, p_wproj, proj_b, p_x1, x, MTOT, CDIM, CDIM);

    // 5) BN2 + pixel-major transpose
    prep_kernel<<<NWIN, 256>>>(p_x1, bn2g, bn2b, bn2m, bn2v, p_xn2, 0,
                               nullptr, nullptr, nullptr, nullptr,
                               nullptr, nullptr, nullptr, nullptr,
                               nullptr, nullptr);

    // 6) FC1 + GELU
    gemm_h<true, 1><<<dim3(CDIM / GBN, MTOT / GBM), NTHR, GEMM_SMEM>>>(
        p_xn2, p_w1, mlp_b1, p_h, nullptr, MTOT, CDIM, CDIM);

    // 7) FC2 + bias + residual -> NCHW f32 output
    gemm_h<true, 2><<<dim3(CDIM / GBN, MTOT / GBM), NTHR, GEMM_SMEM>>>(
        p_h, p_w2, mlp_b2, out, p_x1, MTOT, CDIM, CDIM);
}

// round 12
// speedup vs baseline: 1.3155x; 1.0590x over previous
#include <cuda_runtime.h>
#include <cuda_fp16.h>
#include <mma.h>
#include <cstdint>

using namespace nvcuda;

// ---------------- problem constants ----------------
#define BATCH   8
#define CDIM    512
#define HWDIM   128
#define NWIN    2048
#define MTOT    131072
#define QKVN    1536
#define ATTN_SCALE 0.17677669529663687f   // 32^-0.5
#define AUXBLK  1792                      // cvt (1536) + bias (256) aux blocks

// ---------------- scratch (device globals; no runtime alloc) ----------------
__device__ __half g_xw  [(size_t)MTOT * CDIM];
__device__ __half g_qkv [(size_t)MTOT * QKVN];
__device__ __half g_ctx [(size_t)MTOT * CDIM];
__device__ float  g_x1  [(size_t)MTOT * CDIM];   // NCHW f32
__device__ __half g_xn2 [(size_t)MTOT * CDIM];
__device__ __half g_h   [(size_t)MTOT * CDIM];
__device__ __half g_wqkv [CDIM * QKVN];   // [K,N]
__device__ __half g_wproj[CDIM * CDIM];   // [K,N]
__device__ __half g_w1   [CDIM * CDIM];   // [o,c] = [N,K]
__device__ __half g_w2   [CDIM * CDIM];
__device__ float  g_bias [16 * 64 * 64];  // expanded rel-pos bias [head][n][m]

// =====================================================================
// prep: BN + layout transform -> half; aux blocks do weight-cvt + bias expand.
// Vectorized: float4 loads (NCHW), uint4 (8xhalf) stores.
// window_mode=1: out[(win*64+pix)*512 + c]; 0: out[pixel*512 + c]
// =====================================================================
__global__ __launch_bounds__(256)
void prep_kernel(const float* __restrict__ in,
                 const float* __restrict__ gamma, const float* __restrict__ beta,
                 const float* __restrict__ mean,  const float* __restrict__ var,
                 __half* __restrict__ out, int window_mode,
                 const float* __restrict__ w0, const float* __restrict__ w1,
                 const float* __restrict__ w2, const float* __restrict__ w3,
                 __half* __restrict__ o0, __half* __restrict__ o1,
                 __half* __restrict__ o2, __half* __restrict__ o3,
                 const float* __restrict__ relt, float* __restrict__ biasx)
{
    __shared__ float sscale[CDIM];
    __shared__ float sshift[CDIM];
    __shared__ float tile[64][65];

    int bx  = blockIdx.x;
    int tid = threadIdx.x;

    if (bx >= NWIN) {
        // aux work: weight f32->f16 conversions, then bias expand
        int i = (bx - NWIN) * 256 + tid;            // 0 .. 458751
        if (i < 393216) {
            const float* ip; __half* op; int idx;
            if (i < 196608)      { ip = w0; op = o0; idx = i; }
            else if (i < 262144) { ip = w1; op = o1; idx = i - 196608; }
            else if (i < 327680) { ip = w2; op = o2; idx = i - 262144; }
            else                 { ip = w3; op = o3; idx = i - 327680; }
            float4 v = ((const float4*)ip)[idx];
            __half2* o = (__half2*)op + idx * 2;
            o[0] = __floats2half2_rn(v.x, v.y);
            o[1] = __floats2half2_rn(v.z, v.w);
        } else {
            int idx = i - 393216;                    // 0..65535
            int m = idx & 63;
            int n = (idx >> 6) & 63;
            int h = idx >> 12;
            int i1 = n >> 3, j1 = n & 7;
            int i2 = m >> 3, j2 = m & 7;
            int ridx = (i1 - i2 + 7) * 15 + (j1 - j2 + 7);
            biasx[idx] = relt[ridx * 16 + h];
        }
        return;
    }

    int b   = bx >> 8;
    int hb  = (bx >> 4) & 15;
    int wb  = bx & 15;

    for (int c = tid; c < CDIM; c += 256) {
        float inv = rsqrtf(var[c] + 1e-5f);
        float sc  = gamma[c] * inv;
        sscale[c] = sc;
        sshift[c] = beta[c] - mean[c] * sc;
    }
    __syncthreads();

    int h0 = hb * 8, w0p = wb * 8;
    for (int cc = 0; cc < CDIM; cc += 64) {
        // load phase: 64 ch x 64 pix, float4-vectorized (1024 float4, 4/thread)
        #pragma unroll
        for (int it = 0; it < 4; ++it) {
            int idx = it * 256 + tid;        // 0..1023
            int cl  = idx >> 4;              // 0..63
            int sub = idx & 15;
            int i   = sub >> 1;              // window row 0..7
            int jq  = (sub & 1) * 4;         // 0 or 4
            int c   = cc + cl;
            float sc = sscale[c], sh = sshift[c];
            float4 v = *(const float4*)(in + (((size_t)b * CDIM + c) * HWDIM + h0 + i) * HWDIM + w0p + jq);
            int pix = i * 8 + jq;
            tile[cl][pix + 0] = v.x * sc + sh;
            tile[cl][pix + 1] = v.y * sc + sh;
            tile[cl][pix + 2] = v.z * sc + sh;
            tile[cl][pix + 3] = v.w * sc + sh;
        }
        __syncthreads();
        // store phase: per pixel 64 consecutive halfs = 8 uint4 (512 uint4, 2/thread)
        #pragma unroll
        for (int it = 0; it < 2; ++it) {
            int idx = it * 256 + tid;        // 0..511
            int pix = idx >> 3;              // 0..63
            int q   = idx & 7;               // 8-half group
            float f0 = tile[q * 8 + 0][pix];
            float f1 = tile[q * 8 + 1][pix];
            float f2 = tile[q * 8 + 2][pix];
            float f3 = tile[q * 8 + 3][pix];
            float f4 = tile[q * 8 + 4][pix];
            float f5 = tile[q * 8 + 5][pix];
            float f6 = tile[q * 8 + 6][pix];
            float f7 = tile[q * 8 + 7][pix];
            uint4 pk; __half2 hh;
            hh = __floats2half2_rn(f0, f1); pk.x = *(unsigned*)&hh;
            hh = __floats2half2_rn(f2, f3); pk.y = *(unsigned*)&hh;
            hh = __floats2half2_rn(f4, f5); pk.z = *(unsigned*)&hh;
            hh = __floats2half2_rn(f6, f7); pk.w = *(unsigned*)&hh;
            size_t dst;
            if (window_mode) {
                dst = ((size_t)bx * 64 + pix) * CDIM + cc + q * 8;
            } else {
                int i = pix >> 3, j = pix & 7;
                size_t p = ((size_t)b * HWDIM + h0 + i) * HWDIM + w0p + j;
                dst = p * CDIM + cc + q * 8;
            }
            *(uint4*)(out + dst) = pk;
        }
        __syncthreads();
    }
}

// =====================================================================
// fp16 WMMA GEMM, 2-stage cp.async, 3 CTAs/SM.  (round-8 config)
// Block 128x128x64, 4 warps (2m x 2n), warp tile 64x64.
// EPI: 0 bias->half; 1 bias+GELU->half; 2 bias+f32 res->NCHW f32;
//      3 bias + window-reverse + x residual -> NCHW f32 (proj -> x1).
// =====================================================================
#define GBM 128
#define GBN 128
#define GBK 64
#define NST 2
#define A_LD 72
#define A_ST_BYTES (GBM * A_LD * 2)          // 18432
#define B_ST_BYTES 18432
#define B_LD_ROW 136
#define STG_BYTES (A_ST_BYTES + B_ST_BYTES)  // 36864
#define GEMM_SMEM (NST * STG_BYTES)          // 73728
#define STG_LD 132
#define NTHR 128

__device__ __forceinline__ void cp_async16(void* dst, const void* src) {
    unsigned int d = (unsigned int)__cvta_generic_to_shared(dst);
    asm volatile("cp.async.cg.shared.global [%0], [%1], 16;\n" :: "r"(d), "l"(src));
}
__device__ __forceinline__ void cp_commit() { asm volatile("cp.async.commit_group;\n"); }
template<int W> __device__ __forceinline__ void cp_wait() {
    asm volatile("cp.async.wait_group %0;\n" :: "n"(W));
}

template<bool B_COL, int EPI>
__global__ __launch_bounds__(NTHR, 3)
void gemm_h(const __half* __restrict__ A, const __half* __restrict__ Bm,
            const float* __restrict__ bias, void* __restrict__ Cv,
            const float* __restrict__ res, int M, int N, int K)
{
    extern __shared__ __align__(16) unsigned char smem[];

    int tid  = threadIdx.x;
    int warp = tid >> 5;
    int wm   = warp >> 1;          // 0..1
    int wn   = warp & 1;           // 0..1
    int n0   = blockIdx.x * GBN;
    int m0   = blockIdx.y * GBM;

    wmma::fragment<wmma::accumulator, 16, 16, 16, float> acc[4][4];
    #pragma unroll
    for (int i = 0; i < 4; ++i)
        #pragma unroll
        for (int j = 0; j < 4; ++j)
            wmma::fill_fragment(acc[i][j], 0.0f);

    const int ktiles = K / GBK;

    auto load_tile = [&](int kt, int s) {
        int k0 = kt * GBK;
        __half* As = (__half*)(smem + s * STG_BYTES);
        __half* Bs = (__half*)(smem + s * STG_BYTES + A_ST_BYTES);
        #pragma unroll
        for (int it = 0; it < 8; ++it) {
            int idx = it * NTHR + tid;
            int r = idx >> 3, c8 = idx & 7;
            cp_async16(As + r * A_LD + c8 * 8, A + (size_t)(m0 + r) * K + k0 + c8 * 8);
        }
        if (B_COL) {
            #pragma unroll
            for (int it = 0; it < 8; ++it) {
                int idx = it * NTHR + tid;
                int r = idx >> 3, c8 = idx & 7;
                cp_async16(Bs + r * A_LD + c8 * 8, Bm + (size_t)(n0 + r) * K + k0 + c8 * 8);
            }
        } else {
            #pragma unroll
            for (int it = 0; it < 8; ++it) {
                int idx = it * NTHR + tid;
                int r = idx >> 4, c8 = idx & 15;
                cp_async16(Bs + r * B_LD_ROW + c8 * 8, Bm + (size_t)(k0 + r) * N + n0 + c8 * 8);
            }
        }
        cp_commit();
    };

    load_tile(0, 0);

    for (int t = 0; t < ktiles; ++t) {
        cp_wait<0>();               // stage t loaded
        __syncthreads();            // other stage fully consumed by all warps
        if (t + 1 < ktiles) load_tile(t + 1, (t + 1) & 1);

        int s = t & 1;
        const __half* As = (const __half*)(smem + s * STG_BYTES);
        const __half* Bs = (const __half*)(smem + s * STG_BYTES + A_ST_BYTES);

        #pragma unroll
        for (int kk = 0; kk < 4; ++kk) {
            wmma::fragment<wmma::matrix_a, 16, 16, 16, __half, wmma::row_major> af[4];
            #pragma unroll
            for (int i = 0; i < 4; ++i)
                wmma::load_matrix_sync(af[i], As + (wm * 64 + i * 16) * A_LD + kk * 16, A_LD);
            #pragma unroll
            for (int j = 0; j < 4; ++j) {
                if (B_COL) {
                    wmma::fragment<wmma::matrix_b, 16, 16, 16, __half, wmma::col_major> bf;
                    wmma::load_matrix_sync(bf, Bs + (wn * 64 + j * 16) * A_LD + kk * 16, A_LD);
                    #pragma unroll
                    for (int i = 0; i < 4; ++i)
                        wmma::mma_sync(acc[i][j], af[i], bf, acc[i][j]);
                } else {
                    wmma::fragment<wmma::matrix_b, 16, 16, 16, __half, wmma::row_major> bf;
                    wmma::load_matrix_sync(bf, Bs + (kk * 16) * B_LD_ROW + wn * 64 + j * 16, B_LD_ROW);
                    #pragma unroll
                    for (int i = 0; i < 4; ++i)
                        wmma::mma_sync(acc[i][j], af[i], bf, acc[i][j]);
                }
            }
        }
    }
    __syncthreads();

    // ---------------- epilogue: staging 128x128 f32 ----------------
    float* stg = (float*)smem;        // [128][STG_LD] = 67584 B
    #pragma unroll
    for (int i = 0; i < 4; ++i)
        #pragma unroll
        for (int j = 0; j < 4; ++j)
            wmma::store_matrix_sync(stg + (size_t)(wm * 64 + i * 16) * STG_LD + wn * 64 + j * 16,
                                    acc[i][j], STG_LD, wmma::mem_row_major);
    __syncthreads();

    #pragma unroll
    for (int it = 0; it < 16; ++it) {
        int e = it * (NTHR * 8) + tid * 8;        // 0..16383
        if (EPI == 2) {
            int r = e & 127, col = e >> 7;        // r 8-consecutive
            int n = n0 + col;
            float bv = bias[n];
            int m = m0 + r;
            int bb = m >> 14, hw = m & 16383;
            size_t oi = ((size_t)bb * CDIM + n) * 16384 + hw;
            float4 o0, o1;
            const float4 r0 = *(const float4*)(res + oi);
            const float4 r1 = *(const float4*)(res + oi + 4);
            o0.x = stg[(r+0)*STG_LD+col] + bv + r0.x;
            o0.y = stg[(r+1)*STG_LD+col] + bv + r0.y;
            o0.z = stg[(r+2)*STG_LD+col] + bv + r0.z;
            o0.w = stg[(r+3)*STG_LD+col] + bv + r0.w;
            o1.x = stg[(r+4)*STG_LD+col] + bv + r1.x;
            o1.y = stg[(r+5)*STG_LD+col] + bv + r1.y;
            o1.z = stg[(r+6)*STG_LD+col] + bv + r1.z;
            o1.w = stg[(r+7)*STG_LD+col] + bv + r1.w;
            *(float4*)((float*)Cv + oi)     = o0;
            *(float4*)((float*)Cv + oi + 4) = o1;
        } else {
            int col = e & 127, r = e >> 7;        // col 8-aligned consecutive
            int m = m0 + r;
            int n = n0 + col;
            float v[8];
            #pragma unroll
            for (int j = 0; j < 8; ++j) {
                v[j] = stg[r * STG_LD + col + j] + bias[n + j];
                if (EPI == 1)
                    v[j] = 0.5f * v[j] * (1.0f + erff(v[j] * 0.70710678118654752f));
            }
            if (EPI == 3) {
                int bb  = m >> 14;
                int wl  = (m >> 6) & 255;
                int pix = m & 63;
                int q = wl * 32768 + pix * 512 + n;
                size_t base = (size_t)bb * 8388608 + (size_t)(q >> 14) * 16384
                            + (((q >> 10) & 15) * 8 + ((q >> 3) & 7)) * 128
                            + ((q >> 6) & 15) * 8;
                const float4 x0 = *(const float4*)(res + base);
                const float4 x1v = *(const float4*)(res + base + 4);
                float4 o0 = make_float4(v[0]+x0.x, v[1]+x0.y, v[2]+x0.z, v[3]+x0.w);
                float4 o1 = make_float4(v[4]+x1v.x, v[5]+x1v.y, v[6]+x1v.z, v[7]+x1v.w);
                *(float4*)((float*)Cv + base)     = o0;
                *(float4*)((float*)Cv + base + 4) = o1;
            } else {
                uint4 pk; __half2 hh;
                hh = __floats2half2_rn(v[0], v[1]); pk.x = *(unsigned*)&hh;
                hh = __floats2half2_rn(v[2], v[3]); pk.y = *(unsigned*)&hh;
                hh = __floats2half2_rn(v[4], v[5]); pk.z = *(unsigned*)&hh;
                hh = __floats2half2_rn(v[6], v[7]); pk.w = *(unsigned*)&hh;
                *(uint4*)((__half*)Cv + (size_t)m * N + n) = pk;
            }
        }
    }
}

// =====================================================================
// tensor-core attention: one block per (window, head), 64 threads (2 warps).
// P matrix aliased into S buffer -> 32KB smem/block (6 blocks/SM).
// =====================================================================
#define QK_LD 40    // halfs
#define S_LD  68    // floats
#define P_LDH (S_LD * 2)   // 136 halfs (P aliased over S)

__global__ __launch_bounds__(64)
void attn_tc_kernel(const __half* __restrict__ qkv, const float* __restrict__ bias16,
                    __half* __restrict__ ctx)
{
    __shared__ __align__(16) __half Qs[64 * QK_LD];
    __shared__ __align__(16) __half Ks[64 * QK_LD];
    __shared__ __align__(16) __half Vs[64 * QK_LD];
    __shared__ __align__(16) float  Ss[64 * S_LD];

    int win  = blockIdx.x >> 4;
    int head = blockIdx.x & 15;
    int tid  = threadIdx.x;
    int warp = tid >> 5;

    size_t base = (size_t)win * 64 * QKVN + head * 32;
    #pragma unroll
    for (int i = 0; i < 4; ++i) {
        int idx = i * 64 + tid;
        int tok = idx >> 2, c = idx & 3;
        size_t off = base + (size_t)tok * QKVN + c * 8;
        *(uint4*)(Qs + tok * QK_LD + c * 8) = *(const uint4*)(qkv + off);
        *(uint4*)(Ks + tok * QK_LD + c * 8) = *(const uint4*)(qkv + off + 512);
        *(uint4*)(Vs + tok * QK_LD + c * 8) = *(const uint4*)(qkv + off + 1024);
    }
    __syncthreads();

    // S = Q @ K^T  (64x64x32)
    {
        wmma::fragment<wmma::accumulator, 16, 16, 16, float> sacc[2][4];
        #pragma unroll
        for (int i = 0; i < 2; ++i)
            #pragma unroll
            for (int j = 0; j < 4; ++j)
                wmma::fill_fragment(sacc[i][j], 0.0f);
        #pragma unroll
        for (int kk = 0; kk < 32; kk += 16) {
            wmma::fragment<wmma::matrix_a, 16, 16, 16, __half, wmma::row_major> af[2];
            wmma::fragment<wmma::matrix_b, 16, 16, 16, __half, wmma::col_major> bf[4];
            #pragma unroll
            for (int i = 0; i < 2; ++i)
                wmma::load_matrix_sync(af[i], Qs + (warp * 32 + i * 16) * QK_LD + kk, QK_LD);
            #pragma unroll
            for (int j = 0; j < 4; ++j)
                wmma::load_matrix_sync(bf[j], Ks + (j * 16) * QK_LD + kk, QK_LD);
            #pragma unroll
            for (int i = 0; i < 2; ++i)
                #pragma unroll
                for (int j = 0; j < 4; ++j)
                    wmma::mma_sync(sacc[i][j], af[i], bf[j], sacc[i][j]);
        }
        #pragma unroll
        for (int i = 0; i < 2; ++i)
            #pragma unroll
            for (int j = 0; j < 4; ++j)
                wmma::store_matrix_sync(Ss + (warp * 32 + i * 16) * S_LD + j * 16,
                                        sacc[i][j], S_LD, wmma::mem_row_major);
    }
    __syncthreads();

    // softmax row r = tid (reads full S row into regs, then writes half P over it)
    {
        int r = tid;
        const float* brow = bias16 + ((size_t)head * 64 + r) * 64;
        float v[64];
        float mx = -1e30f;
        #pragma unroll
        for (int q = 0; q < 16; ++q) {
            float4 s = *(float4*)(Ss + r * S_LD + q * 4);
            float4 b = *(const float4*)(brow + q * 4);
            v[q*4+0] = s.x * ATTN_SCALE + b.x;
            v[q*4+1] = s.y * ATTN_SCALE + b.y;
            v[q*4+2] = s.z * ATTN_SCALE + b.z;
            v[q*4+3] = s.w * ATTN_SCALE + b.w;
            mx = fmaxf(mx, fmaxf(fmaxf(v[q*4+0], v[q*4+1]), fmaxf(v[q*4+2], v[q*4+3])));
        }
        float sum = 0.0f;
        #pragma unroll
        for (int m = 0; m < 64; ++m) { v[m] = __expf(v[m] - mx); sum += v[m]; }
        float inv = 1.0f / sum;
        __half* Ps = (__half*)Ss;
        #pragma unroll
        for (int q = 0; q < 8; ++q) {
            uint4 pk; __half2 hh;
            hh = __floats2half2_rn(v[q*8+0]*inv, v[q*8+1]*inv); pk.x = *(unsigned*)&hh;
            hh = __floats2half2_rn(v[q*8+2]*inv, v[q*8+3]*inv); pk.y = *(unsigned*)&hh;
            hh = __floats2half2_rn(v[q*8+4]*inv, v[q*8+5]*inv); pk.z = *(unsigned*)&hh;
            hh = __floats2half2_rn(v[q*8+6]*inv, v[q*8+7]*inv); pk.w = *(unsigned*)&hh;
            *(uint4*)(Ps + r * P_LDH + q * 8) = pk;
        }
    }
    __syncthreads();

    // O = P @ V  (64x32x64)
    {
        const __half* Ps = (const __half*)Ss;
        wmma::fragment<wmma::accumulator, 16, 16, 16, float> oacc[2][2];
        #pragma unroll
        for (int i = 0; i < 2; ++i)
            #pragma unroll
            for (int j = 0; j < 2; ++j)
                wmma::fill_fragment(oacc[i][j], 0.0f);
        #pragma unroll
        for (int kk = 0; kk < 64; kk += 16) {
            wmma::fragment<wmma::matrix_a, 16, 16, 16, __half, wmma::row_major> af[2];
            wmma::fragment<wmma::matrix_b, 16, 16, 16, __half, wmma::row_major> bf[2];
            #pragma unroll
            for (int i = 0; i < 2; ++i)
                wmma::load_matrix_sync(af[i], Ps + (warp * 32 + i * 16) * P_LDH + kk, P_LDH);
            #pragma unroll
            for (int j = 0; j < 2; ++j)
                wmma::load_matrix_sync(bf[j], Vs + kk * QK_LD + j * 16, QK_LD);
            #pragma unroll
            for (int i = 0; i < 2; ++i)
                #pragma unroll
                for (int j = 0; j < 2; ++j)
                    wmma::mma_sync(oacc[i][j], af[i], bf[j], oacc[i][j]);
        }
        // each warp overwrites only its own 32 S rows, after all its P loads
        #pragma unroll
        for (int i = 0; i < 2; ++i)
            #pragma unroll
            for (int j = 0; j < 2; ++j)
                wmma::store_matrix_sync(Ss + (warp * 32 + i * 16) * S_LD + j * 16,
                                        oacc[i][j], S_LD, wmma::mem_row_major);
    }
    __syncthreads();

    {
        int r = tid;
        size_t ob = ((size_t)win * 64 + r) * CDIM + head * 32;
        #pragma unroll
        for (int q = 0; q < 4; ++q) {
            float4 a = *(float4*)(Ss + r * S_LD + q * 8);
            float4 b = *(float4*)(Ss + r * S_LD + q * 8 + 4);
            uint4 pk; __half2 hh;
            hh = __floats2half2_rn(a.x, a.y); pk.x = *(unsigned*)&hh;
            hh = __floats2half2_rn(a.z, a.w); pk.y = *(unsigned*)&hh;
            hh = __floats2half2_rn(b.x, b.y); pk.z = *(unsigned*)&hh;
            hh = __floats2half2_rn(b.z, b.w); pk.w = *(unsigned*)&hh;
            *(uint4*)(ctx + ob + q * 8) = pk;
        }
    }
}

// =====================================================================
extern "C" void kernel_launch(void* const* d_in, const int* in_sizes, int n_in,
                              void* d_out, int out_size)
{
    const float* x      = (const float*)d_in[0];
    const float* qkv_w  = (const float*)d_in[1];
    const float* qkv_b  = (const float*)d_in[2];
    const float* proj_w = (const float*)d_in[3];
    const float* proj_b = (const float*)d_in[4];
    const float* relt   = (const float*)d_in[5];
    const float* bn1g   = (const float*)d_in[6];
    const float* bn1b   = (const float*)d_in[7];
    const float* bn1m   = (const float*)d_in[8];
    const float* bn1v   = (const float*)d_in[9];
    const float* mlp_w1 = (const float*)d_in[10];
    const float* mlp_b1 = (const float*)d_in[11];
    const float* mlp_w2 = (const float*)d_in[12];
    const float* mlp_b2 = (const float*)d_in[13];
    const float* bn2g   = (const float*)d_in[14];
    const float* bn2b   = (const float*)d_in[15];
    const float* bn2m   = (const float*)d_in[16];
    const float* bn2v   = (const float*)d_in[17];
    float* out = (float*)d_out;

    __half *p_xw, *p_qkv, *p_ctx, *p_xn2, *p_h, *p_wqkv, *p_wproj, *p_w1, *p_w2;
    float  *p_x1, *p_bias;
    cudaGetSymbolAddress((void**)&p_xw,   g_xw);
    cudaGetSymbolAddress((void**)&p_qkv,  g_qkv);
    cudaGetSymbolAddress((void**)&p_ctx,  g_ctx);
    cudaGetSymbolAddress((void**)&p_x1,   g_x1);
    cudaGetSymbolAddress((void**)&p_xn2,  g_xn2);
    cudaGetSymbolAddress((void**)&p_h,    g_h);
    cudaGetSymbolAddress((void**)&p_wqkv, g_wqkv);
    cudaGetSymbolAddress((void**)&p_wproj,g_wproj);
    cudaGetSymbolAddress((void**)&p_w1,   g_w1);
    cudaGetSymbolAddress((void**)&p_w2,   g_w2);
    cudaGetSymbolAddress((void**)&p_bias, g_bias);

    cudaFuncSetAttribute(gemm_h<false, 0>, cudaFuncAttributeMaxDynamicSharedMemorySize, GEMM_SMEM);
    cudaFuncSetAttribute(gemm_h<false, 3>, cudaFuncAttributeMaxDynamicSharedMemorySize, GEMM_SMEM);
    cudaFuncSetAttribute(gemm_h<true, 1>,  cudaFuncAttributeMaxDynamicSharedMemorySize, GEMM_SMEM);
    cudaFuncSetAttribute(gemm_h<true, 2>,  cudaFuncAttributeMaxDynamicSharedMemorySize, GEMM_SMEM);

    // 1) BN1 + window partition, with fused weight-cvt + bias-expand aux blocks
    prep_kernel<<<NWIN + AUXBLK, 256>>>(x, bn1g, bn1b, bn1m, bn1v, p_xw, 1,
                                        qkv_w, proj_w, mlp_w1, mlp_w2,
                                        p_wqkv, p_wproj, p_w1, p_w2,
                                        relt, p_bias);

    // 2) QKV projection
    gemm_h<false, 0><<<dim3(QKVN / GBN, MTOT / GBM), NTHR, GEMM_SMEM>>>(
        p_xw, p_wqkv, qkv_b, p_qkv, nullptr, MTOT, QKVN, CDIM);

    // 3) windowed attention (tensor cores)
    attn_tc_kernel<<<NWIN * 16, 64>>>(p_qkv, p_bias, p_ctx);

    // 4) proj + window-reverse + x residual -> x1 (NCHW f32), fused
    gemm_h<false, 3><<<dim3(CDIM / GBN, MTOT / GBM), NTHR, GEMM_SMEM>>>(
        p_ctx, p_wproj, proj_b, p_x1, x, MTOT, CDIM, CDIM);

    // 5) BN2 + pixel-major transpose
    prep_kernel<<<NWIN, 256>>>(p_x1, bn2g, bn2b, bn2m, bn2v, p_xn2, 0,
                               nullptr, nullptr, nullptr, nullptr,
                               nullptr, nullptr, nullptr, nullptr,
                               nullptr, nullptr);

    // 6) FC1 + GELU
    gemm_h<true, 1><<<dim3(CDIM / GBN, MTOT / GBM), NTHR, GEMM_SMEM>>>(
        p_xn2, p_w1, mlp_b1, p_h, nullptr, MTOT, CDIM, CDIM);

    // 7) FC2 + bias + residual -> NCHW f32 output
    gemm_h<true, 2><<<dim3(CDIM / GBN, MTOT / GBM), NTHR, GEMM_SMEM>>>(
        p_h, p_w2, mlp_b2, out, p_x1, MTOT, CDIM, CDIM);
}

// round 13
// speedup vs baseline: 1.3409x; 1.0193x over previous
#include <cuda_runtime.h>
#include <cuda_fp16.h>
#include <mma.h>
#include <cstdint>

using namespace nvcuda;

// ---------------- problem constants ----------------
#define BATCH   8
#define CDIM    512
#define HWDIM   128
#define NWIN    2048
#define MTOT    131072
#define QKVN    1536
#define ATTN_SCALE 0.17677669529663687f   // 32^-0.5
#define AUXBLK  1792                      // cvt (1536) + bias (256) aux blocks

// ---------------- scratch (device globals; no runtime alloc) ----------------
__device__ __half g_xw  [(size_t)MTOT * CDIM];
__device__ __half g_qkv [(size_t)MTOT * QKVN];   // [win][head][sel][tok][32]
__device__ __half g_ctx [(size_t)MTOT * CDIM];
__device__ float  g_x1  [(size_t)MTOT * CDIM];   // NCHW f32
__device__ __half g_xn2 [(size_t)MTOT * CDIM];
__device__ __half g_h   [(size_t)MTOT * CDIM];
__device__ __half g_wqkv [CDIM * QKVN];   // [K,N]
__device__ __half g_wproj[CDIM * CDIM];   // [K,N]
__device__ __half g_w1   [CDIM * CDIM];   // [o,c] = [N,K]
__device__ __half g_w2   [CDIM * CDIM];
__device__ float  g_bias [16 * 64 * 64];  // expanded rel-pos bias [head][n][m]

// =====================================================================
// prep: BN + layout transform -> half; aux blocks do weight-cvt + bias expand.
// Vectorized: float4 loads (NCHW), uint4 (8xhalf) stores.
// window_mode=1: out[(win*64+pix)*512 + c]; 0: out[pixel*512 + c]
// =====================================================================
__global__ __launch_bounds__(256)
void prep_kernel(const float* __restrict__ in,
                 const float* __restrict__ gamma, const float* __restrict__ beta,
                 const float* __restrict__ mean,  const float* __restrict__ var,
                 __half* __restrict__ out, int window_mode,
                 const float* __restrict__ w0, const float* __restrict__ w1,
                 const float* __restrict__ w2, const float* __restrict__ w3,
                 __half* __restrict__ o0, __half* __restrict__ o1,
                 __half* __restrict__ o2, __half* __restrict__ o3,
                 const float* __restrict__ relt, float* __restrict__ biasx)
{
    __shared__ float sscale[CDIM];
    __shared__ float sshift[CDIM];
    __shared__ float tile[64][65];

    int bx  = blockIdx.x;
    int tid = threadIdx.x;

    if (bx >= NWIN) {
        int i = (bx - NWIN) * 256 + tid;            // 0 .. 458751
        if (i < 393216) {
            const float* ip; __half* op; int idx;
            if (i < 196608)      { ip = w0; op = o0; idx = i; }
            else if (i < 262144) { ip = w1; op = o1; idx = i - 196608; }
            else if (i < 327680) { ip = w2; op = o2; idx = i - 262144; }
            else                 { ip = w3; op = o3; idx = i - 327680; }
            float4 v = ((const float4*)ip)[idx];
            __half2* o = (__half2*)op + idx * 2;
            o[0] = __floats2half2_rn(v.x, v.y);
            o[1] = __floats2half2_rn(v.z, v.w);
        } else {
            int idx = i - 393216;                    // 0..65535
            int m = idx & 63;
            int n = (idx >> 6) & 63;
            int h = idx >> 12;
            int i1 = n >> 3, j1 = n & 7;
            int i2 = m >> 3, j2 = m & 7;
            int ridx = (i1 - i2 + 7) * 15 + (j1 - j2 + 7);
            biasx[idx] = relt[ridx * 16 + h];
        }
        return;
    }

    int b   = bx >> 8;
    int hb  = (bx >> 4) & 15;
    int wb  = bx & 15;

    for (int c = tid; c < CDIM; c += 256) {
        float inv = rsqrtf(var[c] + 1e-5f);
        float sc  = gamma[c] * inv;
        sscale[c] = sc;
        sshift[c] = beta[c] - mean[c] * sc;
    }
    __syncthreads();

    int h0 = hb * 8, w0p = wb * 8;
    for (int cc = 0; cc < CDIM; cc += 64) {
        #pragma unroll
        for (int it = 0; it < 4; ++it) {
            int idx = it * 256 + tid;        // 0..1023
            int cl  = idx >> 4;              // 0..63
            int sub = idx & 15;
            int i   = sub >> 1;              // window row 0..7
            int jq  = (sub & 1) * 4;         // 0 or 4
            int c   = cc + cl;
            float sc = sscale[c], sh = sshift[c];
            float4 v = *(const float4*)(in + (((size_t)b * CDIM + c) * HWDIM + h0 + i) * HWDIM + w0p + jq);
            int pix = i * 8 + jq;
            tile[cl][pix + 0] = v.x * sc + sh;
            tile[cl][pix + 1] = v.y * sc + sh;
            tile[cl][pix + 2] = v.z * sc + sh;
            tile[cl][pix + 3] = v.w * sc + sh;
        }
        __syncthreads();
        #pragma unroll
        for (int it = 0; it < 2; ++it) {
            int idx = it * 256 + tid;        // 0..511
            int pix = idx >> 3;              // 0..63
            int q   = idx & 7;               // 8-half group
            float f0 = tile[q * 8 + 0][pix];
            float f1 = tile[q * 8 + 1][pix];
            float f2 = tile[q * 8 + 2][pix];
            float f3 = tile[q * 8 + 3][pix];
            float f4 = tile[q * 8 + 4][pix];
            float f5 = tile[q * 8 + 5][pix];
            float f6 = tile[q * 8 + 6][pix];
            float f7 = tile[q * 8 + 7][pix];
            uint4 pk; __half2 hh;
            hh = __floats2half2_rn(f0, f1); pk.x = *(unsigned*)&hh;
            hh = __floats2half2_rn(f2, f3); pk.y = *(unsigned*)&hh;
            hh = __floats2half2_rn(f4, f5); pk.z = *(unsigned*)&hh;
            hh = __floats2half2_rn(f6, f7); pk.w = *(unsigned*)&hh;
            size_t dst;
            if (window_mode) {
                dst = ((size_t)bx * 64 + pix) * CDIM + cc + q * 8;
            } else {
                int i = pix >> 3, j = pix & 7;
                size_t p = ((size_t)b * HWDIM + h0 + i) * HWDIM + w0p + j;
                dst = p * CDIM + cc + q * 8;
            }
            *(uint4*)(out + dst) = pk;
        }
        __syncthreads();
    }
}

// =====================================================================
// fp16 WMMA GEMM, 2-stage cp.async, 3 CTAs/SM.
// Block 128x128x64, 4 warps (2m x 2n), warp tile 64x64.
// EPI: 0 bias->half [M,N]; 1 bias+GELU->half [M,N]; 2 bias+f32 res->NCHW f32;
//      3 bias + window-reverse + x residual -> NCHW f32 (proj -> x1);
//      4 bias->half, qkv attention layout [win][head][sel][tok][32].
// =====================================================================
#define GBM 128
#define GBN 128
#define GBK 64
#define NST 2
#define A_LD 72
#define A_ST_BYTES (GBM * A_LD * 2)          // 18432
#define B_ST_BYTES 18432
#define B_LD_ROW 136
#define STG_BYTES (A_ST_BYTES + B_ST_BYTES)  // 36864
#define GEMM_SMEM (NST * STG_BYTES)          // 73728
#define STG_LD 132
#define NTHR 128

__device__ __forceinline__ void cp_async16(void* dst, const void* src) {
    unsigned int d = (unsigned int)__cvta_generic_to_shared(dst);
    asm volatile("cp.async.cg.shared.global [%0], [%1], 16;\n" :: "r"(d), "l"(src));
}
__device__ __forceinline__ void cp_commit() { asm volatile("cp.async.commit_group;\n"); }
template<int W> __device__ __forceinline__ void cp_wait() {
    asm volatile("cp.async.wait_group %0;\n" :: "n"(W));
}

template<bool B_COL, int EPI>
__global__ __launch_bounds__(NTHR, 3)
void gemm_h(const __half* __restrict__ A, const __half* __restrict__ Bm,
            const float* __restrict__ bias, void* __restrict__ Cv,
            const float* __restrict__ res, int M, int N, int K)
{
    extern __shared__ __align__(16) unsigned char smem[];

    int tid  = threadIdx.x;
    int warp = tid >> 5;
    int wm   = warp >> 1;          // 0..1
    int wn   = warp & 1;           // 0..1
    int n0   = blockIdx.x * GBN;
    int m0   = blockIdx.y * GBM;

    wmma::fragment<wmma::accumulator, 16, 16, 16, float> acc[4][4];
    #pragma unroll
    for (int i = 0; i < 4; ++i)
        #pragma unroll
        for (int j = 0; j < 4; ++j)
            wmma::fill_fragment(acc[i][j], 0.0f);

    const int ktiles = K / GBK;

    auto load_tile = [&](int kt, int s) {
        int k0 = kt * GBK;
        __half* As = (__half*)(smem + s * STG_BYTES);
        __half* Bs = (__half*)(smem + s * STG_BYTES + A_ST_BYTES);
        #pragma unroll
        for (int it = 0; it < 8; ++it) {
            int idx = it * NTHR + tid;
            int r = idx >> 3, c8 = idx & 7;
            cp_async16(As + r * A_LD + c8 * 8, A + (size_t)(m0 + r) * K + k0 + c8 * 8);
        }
        if (B_COL) {
            #pragma unroll
            for (int it = 0; it < 8; ++it) {
                int idx = it * NTHR + tid;
                int r = idx >> 3, c8 = idx & 7;
                cp_async16(Bs + r * A_LD + c8 * 8, Bm + (size_t)(n0 + r) * K + k0 + c8 * 8);
            }
        } else {
            #pragma unroll
            for (int it = 0; it < 8; ++it) {
                int idx = it * NTHR + tid;
                int r = idx >> 4, c8 = idx & 15;
                cp_async16(Bs + r * B_LD_ROW + c8 * 8, Bm + (size_t)(k0 + r) * N + n0 + c8 * 8);
            }
        }
        cp_commit();
    };

    load_tile(0, 0);

    for (int t = 0; t < ktiles; ++t) {
        cp_wait<0>();               // stage t loaded
        __syncthreads();            // other stage fully consumed by all warps
        if (t + 1 < ktiles) load_tile(t + 1, (t + 1) & 1);

        int s = t & 1;
        const __half* As = (const __half*)(smem + s * STG_BYTES);
        const __half* Bs = (const __half*)(smem + s * STG_BYTES + A_ST_BYTES);

        #pragma unroll
        for (int kk = 0; kk < 4; ++kk) {
            wmma::fragment<wmma::matrix_a, 16, 16, 16, __half, wmma::row_major> af[4];
            #pragma unroll
            for (int i = 0; i < 4; ++i)
                wmma::load_matrix_sync(af[i], As + (wm * 64 + i * 16) * A_LD + kk * 16, A_LD);
            #pragma unroll
            for (int j = 0; j < 4; ++j) {
                if (B_COL) {
                    wmma::fragment<wmma::matrix_b, 16, 16, 16, __half, wmma::col_major> bf;
                    wmma::load_matrix_sync(bf, Bs + (wn * 64 + j * 16) * A_LD + kk * 16, A_LD);
                    #pragma unroll
                    for (int i = 0; i < 4; ++i)
                        wmma::mma_sync(acc[i][j], af[i], bf, acc[i][j]);
                } else {
                    wmma::fragment<wmma::matrix_b, 16, 16, 16, __half, wmma::row_major> bf;
                    wmma::load_matrix_sync(bf, Bs + (kk * 16) * B_LD_ROW + wn * 64 + j * 16, B_LD_ROW);
                    #pragma unroll
                    for (int i = 0; i < 4; ++i)
                        wmma::mma_sync(acc[i][j], af[i], bf, acc[i][j]);
                }
            }
        }
    }
    __syncthreads();

    // ---------------- epilogue: staging 128x128 f32 ----------------
    float* stg = (float*)smem;        // [128][STG_LD] = 67584 B
    #pragma unroll
    for (int i = 0; i < 4; ++i)
        #pragma unroll
        for (int j = 0; j < 4; ++j)
            wmma::store_matrix_sync(stg + (size_t)(wm * 64 + i * 16) * STG_LD + wn * 64 + j * 16,
                                    acc[i][j], STG_LD, wmma::mem_row_major);
    __syncthreads();

    #pragma unroll
    for (int it = 0; it < 16; ++it) {
        int e = it * (NTHR * 8) + tid * 8;        // 0..16383
        if (EPI == 2) {
            int r = e & 127, col = e >> 7;        // r 8-consecutive
            int n = n0 + col;
            float bv = bias[n];
            int m = m0 + r;
            int bb = m >> 14, hw = m & 16383;
            size_t oi = ((size_t)bb * CDIM + n) * 16384 + hw;
            float4 o0, o1;
            const float4 r0 = *(const float4*)(res + oi);
            const float4 r1 = *(const float4*)(res + oi + 4);
            o0.x = stg[(r+0)*STG_LD+col] + bv + r0.x;
            o0.y = stg[(r+1)*STG_LD+col] + bv + r0.y;
            o0.z = stg[(r+2)*STG_LD+col] + bv + r0.z;
            o0.w = stg[(r+3)*STG_LD+col] + bv + r0.w;
            o1.x = stg[(r+4)*STG_LD+col] + bv + r1.x;
            o1.y = stg[(r+5)*STG_LD+col] + bv + r1.y;
            o1.z = stg[(r+6)*STG_LD+col] + bv + r1.z;
            o1.w = stg[(r+7)*STG_LD+col] + bv + r1.w;
            *(float4*)((float*)Cv + oi)     = o0;
            *(float4*)((float*)Cv + oi + 4) = o1;
        } else {
            int col = e & 127, r = e >> 7;        // col 8-aligned consecutive
            int m = m0 + r;
            int n = n0 + col;
            float v[8];
            #pragma unroll
            for (int j = 0; j < 8; ++j) {
                v[j] = stg[r * STG_LD + col + j] + bias[n + j];
                if (EPI == 1)
                    v[j] = 0.5f * v[j] * (1.0f + erff(v[j] * 0.70710678118654752f));
            }
            if (EPI == 3) {
                int bb  = m >> 14;
                int wl  = (m >> 6) & 255;
                int pix = m & 63;
                int q = wl * 32768 + pix * 512 + n;
                size_t base = (size_t)bb * 8388608 + (size_t)(q >> 14) * 16384
                            + (((q >> 10) & 15) * 8 + ((q >> 3) & 7)) * 128
                            + ((q >> 6) & 15) * 8;
                const float4 x0 = *(const float4*)(res + base);
                const float4 x1v = *(const float4*)(res + base + 4);
                float4 o0 = make_float4(v[0]+x0.x, v[1]+x0.y, v[2]+x0.z, v[3]+x0.w);
                float4 o1 = make_float4(v[4]+x1v.x, v[5]+x1v.y, v[6]+x1v.z, v[7]+x1v.w);
                *(float4*)((float*)Cv + base)     = o0;
                *(float4*)((float*)Cv + base + 4) = o1;
            } else {
                uint4 pk; __half2 hh;
                hh = __floats2half2_rn(v[0], v[1]); pk.x = *(unsigned*)&hh;
                hh = __floats2half2_rn(v[2], v[3]); pk.y = *(unsigned*)&hh;
                hh = __floats2half2_rn(v[4], v[5]); pk.z = *(unsigned*)&hh;
                hh = __floats2half2_rn(v[6], v[7]); pk.w = *(unsigned*)&hh;
                if (EPI == 4) {
                    // attention layout: [win][head][sel][tok=pix][32]
                    int win = m >> 6, pix = m & 63;
                    int sel = n >> 9;              // n / 512
                    int head = (n >> 5) & 15;      // (n % 512) / 32
                    int d = n & 31;
                    size_t dst = (((size_t)(win * 16 + head) * 3 + sel) * 64 + pix) * 32 + d;
                    *(uint4*)((__half*)Cv + dst) = pk;
                } else {
                    *(uint4*)((__half*)Cv + (size_t)m * N + n) = pk;
                }
            }
        }
    }
}

// =====================================================================
// tensor-core attention: one block per (window, head), 64 threads (2 warps).
// QKV read as 3 contiguous 4KB blocks (EPI4 layout).
// P matrix aliased into S buffer -> 32KB smem/block (6 blocks/SM).
// =====================================================================
#define QK_LD 40    // halfs
#define S_LD  68    // floats
#define P_LDH (S_LD * 2)   // 136 halfs (P aliased over S)

__global__ __launch_bounds__(64)
void attn_tc_kernel(const __half* __restrict__ qkv, const float* __restrict__ bias16,
                    __half* __restrict__ ctx)
{
    __shared__ __align__(16) __half Qs[64 * QK_LD];
    __shared__ __align__(16) __half Ks[64 * QK_LD];
    __shared__ __align__(16) __half Vs[64 * QK_LD];
    __shared__ __align__(16) float  Ss[64 * S_LD];

    int win  = blockIdx.x >> 4;
    int head = blockIdx.x & 15;
    int tid  = threadIdx.x;
    int warp = tid >> 5;

    // contiguous loads: Q/K/V each 2048 halfs = 256 uint4
    size_t qbase = (size_t)(win * 16 + head) * 3 * 2048;
    #pragma unroll
    for (int i = 0; i < 4; ++i) {
        int idx = i * 64 + tid;            // uint4 index 0..255
        int e = idx * 8;                   // half index
        int tok = e >> 5, d = e & 31;
        uint32_t so = tok * QK_LD + d;
        *(uint4*)(Qs + so) = *(const uint4*)(qkv + qbase + e);
        *(uint4*)(Ks + so) = *(const uint4*)(qkv + qbase + 2048 + e);
        *(uint4*)(Vs + so) = *(const uint4*)(qkv + qbase + 4096 + e);
    }
    __syncthreads();

    // S = Q @ K^T  (64x64x32)
    {
        wmma::fragment<wmma::accumulator, 16, 16, 16, float> sacc[2][4];
        #pragma unroll
        for (int i = 0; i < 2; ++i)
            #pragma unroll
            for (int j = 0; j < 4; ++j)
                wmma::fill_fragment(sacc[i][j], 0.0f);
        #pragma unroll
        for (int kk = 0; kk < 32; kk += 16) {
            wmma::fragment<wmma::matrix_a, 16, 16, 16, __half, wmma::row_major> af[2];
            wmma::fragment<wmma::matrix_b, 16, 16, 16, __half, wmma::col_major> bf[4];
            #pragma unroll
            for (int i = 0; i < 2; ++i)
                wmma::load_matrix_sync(af[i], Qs + (warp * 32 + i * 16) * QK_LD + kk, QK_LD);
            #pragma unroll
            for (int j = 0; j < 4; ++j)
                wmma::load_matrix_sync(bf[j], Ks + (j * 16) * QK_LD + kk, QK_LD);
            #pragma unroll
            for (int i = 0; i < 2; ++i)
                #pragma unroll
                for (int j = 0; j < 4; ++j)
                    wmma::mma_sync(sacc[i][j], af[i], bf[j], sacc[i][j]);
        }
        #pragma unroll
        for (int i = 0; i < 2; ++i)
            #pragma unroll
            for (int j = 0; j < 4; ++j)
                wmma::store_matrix_sync(Ss + (warp * 32 + i * 16) * S_LD + j * 16,
                                        sacc[i][j], S_LD, wmma::mem_row_major);
    }
    __syncthreads();

    // softmax row r = tid (reads full S row into regs, then writes half P over it)
    {
        int r = tid;
        const float* brow = bias16 + ((size_t)head * 64 + r) * 64;
        float v[64];
        float mx = -1e30f;
        #pragma unroll
        for (int q = 0; q < 16; ++q) {
            float4 s = *(float4*)(Ss + r * S_LD + q * 4);
            float4 b = *(const float4*)(brow + q * 4);
            v[q*4+0] = s.x * ATTN_SCALE + b.x;
            v[q*4+1] = s.y * ATTN_SCALE + b.y;
            v[q*4+2] = s.z * ATTN_SCALE + b.z;
            v[q*4+3] = s.w * ATTN_SCALE + b.w;
            mx = fmaxf(mx, fmaxf(fmaxf(v[q*4+0], v[q*4+1]), fmaxf(v[q*4+2], v[q*4+3])));
        }
        float sum = 0.0f;
        #pragma unroll
        for (int m = 0; m < 64; ++m) { v[m] = __expf(v[m] - mx); sum += v[m]; }
        float inv = 1.0f / sum;
        __half* Ps = (__half*)Ss;
        #pragma unroll
        for (int q = 0; q < 8; ++q) {
            uint4 pk; __half2 hh;
            hh = __floats2half2_rn(v[q*8+0]*inv, v[q*8+1]*inv); pk.x = *(unsigned*)&hh;
            hh = __floats2half2_rn(v[q*8+2]*inv, v[q*8+3]*inv); pk.y = *(unsigned*)&hh;
            hh = __floats2half2_rn(v[q*8+4]*inv, v[q*8+5]*inv); pk.z = *(unsigned*)&hh;
            hh = __floats2half2_rn(v[q*8+6]*inv, v[q*8+7]*inv); pk.w = *(unsigned*)&hh;
            *(uint4*)(Ps + r * P_LDH + q * 8) = pk;
        }
    }
    __syncthreads();

    // O = P @ V  (64x32x64)
    {
        const __half* Ps = (const __half*)Ss;
        wmma::fragment<wmma::accumulator, 16, 16, 16, float> oacc[2][2];
        #pragma unroll
        for (int i = 0; i < 2; ++i)
            #pragma unroll
            for (int j = 0; j < 2; ++j)
                wmma::fill_fragment(oacc[i][j], 0.0f);
        #pragma unroll
        for (int kk = 0; kk < 64; kk += 16) {
            wmma::fragment<wmma::matrix_a, 16, 16, 16, __half, wmma::row_major> af[2];
            wmma::fragment<wmma::matrix_b, 16, 16, 16, __half, wmma::row_major> bf[2];
            #pragma unroll
            for (int i = 0; i < 2; ++i)
                wmma::load_matrix_sync(af[i], Ps + (warp * 32 + i * 16) * P_LDH + kk, P_LDH);
            #pragma unroll
            for (int j = 0; j < 2; ++j)
                wmma::load_matrix_sync(bf[j], Vs + kk * QK_LD + j * 16, QK_LD);
            #pragma unroll
            for (int i = 0; i < 2; ++i)
                #pragma unroll
                for (int j = 0; j < 2; ++j)
                    wmma::mma_sync(oacc[i][j], af[i], bf[j], oacc[i][j]);
        }
        #pragma unroll
        for (int i = 0; i < 2; ++i)
            #pragma unroll
            for (int j = 0; j < 2; ++j)
                wmma::store_matrix_sync(Ss + (warp * 32 + i * 16) * S_LD + j * 16,
                                        oacc[i][j], S_LD, wmma::mem_row_major);
    }
    __syncthreads();

    {
        int r = tid;
        size_t ob = ((size_t)win * 64 + r) * CDIM + head * 32;
        #pragma unroll
        for (int q = 0; q < 4; ++q) {
            float4 a = *(float4*)(Ss + r * S_LD + q * 8);
            float4 b = *(float4*)(Ss + r * S_LD + q * 8 + 4);
            uint4 pk; __half2 hh;
            hh = __floats2half2_rn(a.x, a.y); pk.x = *(unsigned*)&hh;
            hh = __floats2half2_rn(a.z, a.w); pk.y = *(unsigned*)&hh;
            hh = __floats2half2_rn(b.x, b.y); pk.z = *(unsigned*)&hh;
            hh = __floats2half2_rn(b.z, b.w); pk.w = *(unsigned*)&hh;
            *(uint4*)(ctx + ob + q * 8) = pk;
        }
    }
}

// =====================================================================
extern "C" void kernel_launch(void* const* d_in, const int* in_sizes, int n_in,
                              void* d_out, int out_size)
{
    const float* x      = (const float*)d_in[0];
    const float* qkv_w  = (const float*)d_in[1];
    const float* qkv_b  = (const float*)d_in[2];
    const float* proj_w = (const float*)d_in[3];
    const float* proj_b = (const float*)d_in[4];
    const float* relt   = (const float*)d_in[5];
    const float* bn1g   = (const float*)d_in[6];
    const float* bn1b   = (const float*)d_in[7];
    const float* bn1m   = (const float*)d_in[8];
    const float* bn1v   = (const float*)d_in[9];
    const float* mlp_w1 = (const float*)d_in[10];
    const float* mlp_b1 = (const float*)d_in[11];
    const float* mlp_w2 = (const float*)d_in[12];
    const float* mlp_b2 = (const float*)d_in[13];
    const float* bn2g   = (const float*)d_in[14];
    const float* bn2b   = (const float*)d_in[15];
    const float* bn2m   = (const float*)d_in[16];
    const float* bn2v   = (const float*)d_in[17];
    float* out = (float*)d_out;

    __half *p_xw, *p_qkv, *p_ctx, *p_xn2, *p_h, *p_wqkv, *p_wproj, *p_w1, *p_w2;
    float  *p_x1, *p_bias;
    cudaGetSymbolAddress((void**)&p_xw,   g_xw);
    cudaGetSymbolAddress((void**)&p_qkv,  g_qkv);
    cudaGetSymbolAddress((void**)&p_ctx,  g_ctx);
    cudaGetSymbolAddress((void**)&p_x1,   g_x1);
    cudaGetSymbolAddress((void**)&p_xn2,  g_xn2);
    cudaGetSymbolAddress((void**)&p_h,    g_h);
    cudaGetSymbolAddress((void**)&p_wqkv, g_wqkv);
    cudaGetSymbolAddress((void**)&p_wproj,g_wproj);
    cudaGetSymbolAddress((void**)&p_w1,   g_w1);
    cudaGetSymbolAddress((void**)&p_w2,   g_w2);
    cudaGetSymbolAddress((void**)&p_bias, g_bias);

    cudaFuncSetAttribute(gemm_h<false, 4>, cudaFuncAttributeMaxDynamicSharedMemorySize, GEMM_SMEM);
    cudaFuncSetAttribute(gemm_h<false, 3>, cudaFuncAttributeMaxDynamicSharedMemorySize, GEMM_SMEM);
    cudaFuncSetAttribute(gemm_h<true, 1>,  cudaFuncAttributeMaxDynamicSharedMemorySize, GEMM_SMEM);
    cudaFuncSetAttribute(gemm_h<true, 2>,  cudaFuncAttributeMaxDynamicSharedMemorySize, GEMM_SMEM);

    // 1) BN1 + window partition, with fused weight-cvt + bias-expand aux blocks
    prep_kernel<<<NWIN + AUXBLK, 256>>>(x, bn1g, bn1b, bn1m, bn1v, p_xw, 1,
                                        qkv_w, proj_w, mlp_w1, mlp_w2,
                                        p_wqkv, p_wproj, p_w1, p_w2,
                                        relt, p_bias);

    // 2) QKV projection -> attention-friendly layout
    gemm_h<false, 4><<<dim3(QKVN / GBN, MTOT / GBM), NTHR, GEMM_SMEM>>>(
        p_xw, p_wqkv, qkv_b, p_qkv, nullptr, MTOT, QKVN, CDIM);

    // 3) windowed attention (tensor cores, coalesced loads)
    attn_tc_kernel<<<NWIN * 16, 64>>>(p_qkv, p_bias, p_ctx);

    // 4) proj + window-reverse + x residual -> x1 (NCHW f32), fused
    gemm_h<false, 3><<<dim3(CDIM / GBN, MTOT / GBM), NTHR, GEMM_SMEM>>>(
        p_ctx, p_wproj, proj_b, p_x1, x, MTOT, CDIM, CDIM);

    // 5) BN2 + pixel-major transpose
    prep_kernel<<<NWIN, 256>>>(p_x1, bn2g, bn2b, bn2m, bn2v, p_xn2, 0,
                               nullptr, nullptr, nullptr, nullptr,
                               nullptr, nullptr, nullptr, nullptr,
                               nullptr, nullptr);

    // 6) FC1 + GELU
    gemm_h<true, 1><<<dim3(CDIM / GBN, MTOT / GBM), NTHR, GEMM_SMEM>>>(
        p_xn2, p_w1, mlp_b1, p_h, nullptr, MTOT, CDIM, CDIM);

    // 7) FC2 + bias + residual -> NCHW f32 output
    gemm_h<true, 2><<<dim3(CDIM / GBN, MTOT / GBM), NTHR, GEMM_SMEM>>>(
        p_h, p_w2, mlp_b2, out, p_x1, MTOT, CDIM, CDIM);
}

// round 14
// speedup vs baseline: 1.3646x; 1.0177x over previous
#include <cuda_runtime.h>
#include <cuda_fp16.h>
#include <mma.h>
#include <cstdint>

using namespace nvcuda;

// ---------------- problem constants ----------------
#define BATCH   8
#define CDIM    512
#define HWDIM   128
#define NWIN    2048
#define MTOT    131072
#define QKVN    1536
#define ATTN_SCALE 0.17677669529663687f   // 32^-0.5
#define AUXBLK  1792                      // cvt (1536) + bias (256) aux blocks

// ---------------- scratch (device globals; no runtime alloc) ----------------
__device__ __half g_xw  [(size_t)MTOT * CDIM];
__device__ __half g_qkv [(size_t)MTOT * QKVN];   // [win][head][sel][tok][32]
__device__ __half g_ctx [(size_t)MTOT * CDIM];
__device__ float  g_x1  [(size_t)MTOT * CDIM];   // NCHW f32
__device__ __half g_xn2 [(size_t)MTOT * CDIM];
__device__ __half g_h   [(size_t)MTOT * CDIM];
__device__ __half g_wqkv [CDIM * QKVN];   // [K,N]
__device__ __half g_wproj[CDIM * CDIM];   // [K,N]
__device__ __half g_w1   [CDIM * CDIM];   // [o,c] = [N,K]
__device__ __half g_w2   [CDIM * CDIM];
__device__ float  g_bias [16 * 64 * 64];  // expanded rel-pos bias [head][n][m]

// =====================================================================
// prep: BN + layout transform -> half; aux blocks do weight-cvt + bias expand.
// =====================================================================
__global__ __launch_bounds__(256)
void prep_kernel(const float* __restrict__ in,
                 const float* __restrict__ gamma, const float* __restrict__ beta,
                 const float* __restrict__ mean,  const float* __restrict__ var,
                 __half* __restrict__ out, int window_mode,
                 const float* __restrict__ w0, const float* __restrict__ w1,
                 const float* __restrict__ w2, const float* __restrict__ w3,
                 __half* __restrict__ o0, __half* __restrict__ o1,
                 __half* __restrict__ o2, __half* __restrict__ o3,
                 const float* __restrict__ relt, float* __restrict__ biasx)
{
    __shared__ float sscale[CDIM];
    __shared__ float sshift[CDIM];
    __shared__ float tile[64][65];

    int bx  = blockIdx.x;
    int tid = threadIdx.x;

    if (bx >= NWIN) {
        int i = (bx - NWIN) * 256 + tid;            // 0 .. 458751
        if (i < 393216) {
            const float* ip; __half* op; int idx;
            if (i < 196608)      { ip = w0; op = o0; idx = i; }
            else if (i < 262144) { ip = w1; op = o1; idx = i - 196608; }
            else if (i < 327680) { ip = w2; op = o2; idx = i - 262144; }
            else                 { ip = w3; op = o3; idx = i - 327680; }
            float4 v = ((const float4*)ip)[idx];
            __half2* o = (__half2*)op + idx * 2;
            o[0] = __floats2half2_rn(v.x, v.y);
            o[1] = __floats2half2_rn(v.z, v.w);
        } else {
            int idx = i - 393216;                    // 0..65535
            int m = idx & 63;
            int n = (idx >> 6) & 63;
            int h = idx >> 12;
            int i1 = n >> 3, j1 = n & 7;
            int i2 = m >> 3, j2 = m & 7;
            int ridx = (i1 - i2 + 7) * 15 + (j1 - j2 + 7);
            biasx[idx] = relt[ridx * 16 + h];
        }
        return;
    }

    int b   = bx >> 8;
    int hb  = (bx >> 4) & 15;
    int wb  = bx & 15;

    for (int c = tid; c < CDIM; c += 256) {
        float inv = rsqrtf(var[c] + 1e-5f);
        float sc  = gamma[c] * inv;
        sscale[c] = sc;
        sshift[c] = beta[c] - mean[c] * sc;
    }
    __syncthreads();

    int h0 = hb * 8, w0p = wb * 8;
    for (int cc = 0; cc < CDIM; cc += 64) {
        #pragma unroll
        for (int it = 0; it < 4; ++it) {
            int idx = it * 256 + tid;        // 0..1023
            int cl  = idx >> 4;
            int sub = idx & 15;
            int i   = sub >> 1;
            int jq  = (sub & 1) * 4;
            int c   = cc + cl;
            float sc = sscale[c], sh = sshift[c];
            float4 v = *(const float4*)(in + (((size_t)b * CDIM + c) * HWDIM + h0 + i) * HWDIM + w0p + jq);
            int pix = i * 8 + jq;
            tile[cl][pix + 0] = v.x * sc + sh;
            tile[cl][pix + 1] = v.y * sc + sh;
            tile[cl][pix + 2] = v.z * sc + sh;
            tile[cl][pix + 3] = v.w * sc + sh;
        }
        __syncthreads();
        #pragma unroll
        for (int it = 0; it < 2; ++it) {
            int idx = it * 256 + tid;        // 0..511
            int pix = idx >> 3;
            int q   = idx & 7;
            float f0 = tile[q * 8 + 0][pix];
            float f1 = tile[q * 8 + 1][pix];
            float f2 = tile[q * 8 + 2][pix];
            float f3 = tile[q * 8 + 3][pix];
            float f4 = tile[q * 8 + 4][pix];
            float f5 = tile[q * 8 + 5][pix];
            float f6 = tile[q * 8 + 6][pix];
            float f7 = tile[q * 8 + 7][pix];
            uint4 pk; __half2 hh;
            hh = __floats2half2_rn(f0, f1); pk.x = *(unsigned*)&hh;
            hh = __floats2half2_rn(f2, f3); pk.y = *(unsigned*)&hh;
            hh = __floats2half2_rn(f4, f5); pk.z = *(unsigned*)&hh;
            hh = __floats2half2_rn(f6, f7); pk.w = *(unsigned*)&hh;
            size_t dst;
            if (window_mode) {
                dst = ((size_t)bx * 64 + pix) * CDIM + cc + q * 8;
            } else {
                int i = pix >> 3, j = pix & 7;
                size_t p = ((size_t)b * HWDIM + h0 + i) * HWDIM + w0p + j;
                dst = p * CDIM + cc + q * 8;
            }
            *(uint4*)(out + dst) = pk;
        }
        __syncthreads();
    }
}

// =====================================================================
// fp16 WMMA GEMM, 2-stage cp.async, 3 CTAs/SM.
// EPI: 0 bias->half [M,N]; 1 bias+GELU->half; 2 bias+f32 res->NCHW f32;
//      3 bias + window-reverse + x residual -> NCHW f32 (proj -> x1);
//      4 bias->half, qkv attention layout [win][head][sel][tok][32].
// =====================================================================
#define GBM 128
#define GBN 128
#define GBK 64
#define NST 2
#define A_LD 72
#define A_ST_BYTES (GBM * A_LD * 2)
#define B_ST_BYTES 18432
#define B_LD_ROW 136
#define STG_BYTES (A_ST_BYTES + B_ST_BYTES)
#define GEMM_SMEM (NST * STG_BYTES)
#define STG_LD 132
#define NTHR 128

__device__ __forceinline__ void cp_async16(void* dst, const void* src) {
    unsigned int d = (unsigned int)__cvta_generic_to_shared(dst);
    asm volatile("cp.async.cg.shared.global [%0], [%1], 16;\n" :: "r"(d), "l"(src));
}
__device__ __forceinline__ void cp_commit() { asm volatile("cp.async.commit_group;\n"); }
template<int W> __device__ __forceinline__ void cp_wait() {
    asm volatile("cp.async.wait_group %0;\n" :: "n"(W));
}

template<bool B_COL, int EPI>
__global__ __launch_bounds__(NTHR, 3)
void gemm_h(const __half* __restrict__ A, const __half* __restrict__ Bm,
            const float* __restrict__ bias, void* __restrict__ Cv,
            const float* __restrict__ res, int M, int N, int K)
{
    extern __shared__ __align__(16) unsigned char smem[];

    int tid  = threadIdx.x;
    int warp = tid >> 5;
    int wm   = warp >> 1;
    int wn   = warp & 1;
    int n0   = blockIdx.x * GBN;
    int m0   = blockIdx.y * GBM;

    wmma::fragment<wmma::accumulator, 16, 16, 16, float> acc[4][4];
    #pragma unroll
    for (int i = 0; i < 4; ++i)
        #pragma unroll
        for (int j = 0; j < 4; ++j)
            wmma::fill_fragment(acc[i][j], 0.0f);

    const int ktiles = K / GBK;

    auto load_tile = [&](int kt, int s) {
        int k0 = kt * GBK;
        __half* As = (__half*)(smem + s * STG_BYTES);
        __half* Bs = (__half*)(smem + s * STG_BYTES + A_ST_BYTES);
        #pragma unroll
        for (int it = 0; it < 8; ++it) {
            int idx = it * NTHR + tid;
            int r = idx >> 3, c8 = idx & 7;
            cp_async16(As + r * A_LD + c8 * 8, A + (size_t)(m0 + r) * K + k0 + c8 * 8);
        }
        if (B_COL) {
            #pragma unroll
            for (int it = 0; it < 8; ++it) {
                int idx = it * NTHR + tid;
                int r = idx >> 3, c8 = idx & 7;
                cp_async16(Bs + r * A_LD + c8 * 8, Bm + (size_t)(n0 + r) * K + k0 + c8 * 8);
            }
        } else {
            #pragma unroll
            for (int it = 0; it < 8; ++it) {
                int idx = it * NTHR + tid;
                int r = idx >> 4, c8 = idx & 15;
                cp_async16(Bs + r * B_LD_ROW + c8 * 8, Bm + (size_t)(k0 + r) * N + n0 + c8 * 8);
            }
        }
        cp_commit();
    };

    load_tile(0, 0);

    for (int t = 0; t < ktiles; ++t) {
        cp_wait<0>();
        __syncthreads();
        if (t + 1 < ktiles) load_tile(t + 1, (t + 1) & 1);

        int s = t & 1;
        const __half* As = (const __half*)(smem + s * STG_BYTES);
        const __half* Bs = (const __half*)(smem + s * STG_BYTES + A_ST_BYTES);

        #pragma unroll
        for (int kk = 0; kk < 4; ++kk) {
            wmma::fragment<wmma::matrix_a, 16, 16, 16, __half, wmma::row_major> af[4];
            #pragma unroll
            for (int i = 0; i < 4; ++i)
                wmma::load_matrix_sync(af[i], As + (wm * 64 + i * 16) * A_LD + kk * 16, A_LD);
            #pragma unroll
            for (int j = 0; j < 4; ++j) {
                if (B_COL) {
                    wmma::fragment<wmma::matrix_b, 16, 16, 16, __half, wmma::col_major> bf;
                    wmma::load_matrix_sync(bf, Bs + (wn * 64 + j * 16) * A_LD + kk * 16, A_LD);
                    #pragma unroll
                    for (int i = 0; i < 4; ++i)
                        wmma::mma_sync(acc[i][j], af[i], bf, acc[i][j]);
                } else {
                    wmma::fragment<wmma::matrix_b, 16, 16, 16, __half, wmma::row_major> bf;
                    wmma::load_matrix_sync(bf, Bs + (kk * 16) * B_LD_ROW + wn * 64 + j * 16, B_LD_ROW);
                    #pragma unroll
                    for (int i = 0; i < 4; ++i)
                        wmma::mma_sync(acc[i][j], af[i], bf, acc[i][j]);
                }
            }
        }
    }
    __syncthreads();

    float* stg = (float*)smem;
    #pragma unroll
    for (int i = 0; i < 4; ++i)
        #pragma unroll
        for (int j = 0; j < 4; ++j)
            wmma::store_matrix_sync(stg + (size_t)(wm * 64 + i * 16) * STG_LD + wn * 64 + j * 16,
                                    acc[i][j], STG_LD, wmma::mem_row_major);
    __syncthreads();

    #pragma unroll
    for (int it = 0; it < 16; ++it) {
        int e = it * (NTHR * 8) + tid * 8;
        if (EPI == 2) {
            int r = e & 127, col = e >> 7;
            int n = n0 + col;
            float bv = bias[n];
            int m = m0 + r;
            int bb = m >> 14, hw = m & 16383;
            size_t oi = ((size_t)bb * CDIM + n) * 16384 + hw;
            float4 o0, o1;
            const float4 r0 = *(const float4*)(res + oi);
            const float4 r1 = *(const float4*)(res + oi + 4);
            o0.x = stg[(r+0)*STG_LD+col] + bv + r0.x;
            o0.y = stg[(r+1)*STG_LD+col] + bv + r0.y;
            o0.z = stg[(r+2)*STG_LD+col] + bv + r0.z;
            o0.w = stg[(r+3)*STG_LD+col] + bv + r0.w;
            o1.x = stg[(r+4)*STG_LD+col] + bv + r1.x;
            o1.y = stg[(r+5)*STG_LD+col] + bv + r1.y;
            o1.z = stg[(r+6)*STG_LD+col] + bv + r1.z;
            o1.w = stg[(r+7)*STG_LD+col] + bv + r1.w;
            *(float4*)((float*)Cv + oi)     = o0;
            *(float4*)((float*)Cv + oi + 4) = o1;
        } else {
            int col = e & 127, r = e >> 7;
            int m = m0 + r;
            int n = n0 + col;
            float v[8];
            #pragma unroll
            for (int j = 0; j < 8; ++j) {
                v[j] = stg[r * STG_LD + col + j] + bias[n + j];
                if (EPI == 1)
                    v[j] = 0.5f * v[j] * (1.0f + erff(v[j] * 0.70710678118654752f));
            }
            if (EPI == 3) {
                int bb  = m >> 14;
                int wl  = (m >> 6) & 255;
                int pix = m & 63;
                int q = wl * 32768 + pix * 512 + n;
                size_t base = (size_t)bb * 8388608 + (size_t)(q >> 14) * 16384
                            + (((q >> 10) & 15) * 8 + ((q >> 3) & 7)) * 128
                            + ((q >> 6) & 15) * 8;
                const float4 x0 = *(const float4*)(res + base);
                const float4 x1v = *(const float4*)(res + base + 4);
                float4 o0 = make_float4(v[0]+x0.x, v[1]+x0.y, v[2]+x0.z, v[3]+x0.w);
                float4 o1 = make_float4(v[4]+x1v.x, v[5]+x1v.y, v[6]+x1v.z, v[7]+x1v.w);
                *(float4*)((float*)Cv + base)     = o0;
                *(float4*)((float*)Cv + base + 4) = o1;
            } else {
                uint4 pk; __half2 hh;
                hh = __floats2half2_rn(v[0], v[1]); pk.x = *(unsigned*)&hh;
                hh = __floats2half2_rn(v[2], v[3]); pk.y = *(unsigned*)&hh;
                hh = __floats2half2_rn(v[4], v[5]); pk.z = *(unsigned*)&hh;
                hh = __floats2half2_rn(v[6], v[7]); pk.w = *(unsigned*)&hh;
                if (EPI == 4) {
                    int win = m >> 6, pix = m & 63;
                    int sel = n >> 9;
                    int head = (n >> 5) & 15;
                    int d = n & 31;
                    size_t dst = (((size_t)(win * 16 + head) * 3 + sel) * 64 + pix) * 32 + d;
                    *(uint4*)((__half*)Cv + dst) = pk;
                } else {
                    *(uint4*)((__half*)Cv + (size_t)m * N + n) = pk;
                }
            }
        }
    }
}

// =====================================================================
// tensor-core attention v2: one block per (window, head-pair), 64 threads.
// Two heads processed sequentially; head 1's QKV prefetched via cp.async
// into a second buffer while head 0 computes. 47KB smem -> 4 blocks/SM.
// =====================================================================
#define QK_LD 40            // halfs
#define ABUF_H 7680         // 3 * 64 * QK_LD  (Q@0, K@2560, V@5120)
#define S_LD  68            // floats
#define P_LDH (S_LD * 2)    // 136 halfs (P aliased over S)

__global__ __launch_bounds__(64)
void attn_tc_kernel(const __half* __restrict__ qkv, const float* __restrict__ bias16,
                    __half* __restrict__ ctx)
{
    __shared__ __align__(16) __half buf[2][ABUF_H];
    __shared__ __align__(16) float  Ss[64 * S_LD];

    int win   = blockIdx.x >> 3;
    int hpair = blockIdx.x & 7;
    int tid   = threadIdx.x;
    int warp  = tid >> 5;

    auto loadh = [&](int bi, int head) {
        size_t qb = (size_t)(win * 16 + head) * 3 * 2048;
        #pragma unroll
        for (int mat = 0; mat < 3; ++mat) {
            #pragma unroll
            for (int i = 0; i < 4; ++i) {
                int idx = i * 64 + tid;       // uint4 idx 0..255
                int e = idx * 8;
                int tok = e >> 5, d = e & 31;
                cp_async16(buf[bi] + mat * 2560 + tok * QK_LD + d,
                           qkv + qb + mat * 2048 + e);
            }
        }
        cp_commit();
    };

    loadh(0, hpair * 2);
    loadh(1, hpair * 2 + 1);

    for (int h = 0; h < 2; ++h) {
        if (h == 0) cp_wait<1>(); else cp_wait<0>();
        __syncthreads();

        int head = hpair * 2 + h;
        const __half* Qs = buf[h];
        const __half* Ks = buf[h] + 2560;
        const __half* Vs = buf[h] + 5120;

        // S = Q @ K^T  (64x64x32)
        {
            wmma::fragment<wmma::accumulator, 16, 16, 16, float> sacc[2][4];
            #pragma unroll
            for (int i = 0; i < 2; ++i)
                #pragma unroll
                for (int j = 0; j < 4; ++j)
                    wmma::fill_fragment(sacc[i][j], 0.0f);
            #pragma unroll
            for (int kk = 0; kk < 32; kk += 16) {
                wmma::fragment<wmma::matrix_a, 16, 16, 16, __half, wmma::row_major> af[2];
                wmma::fragment<wmma::matrix_b, 16, 16, 16, __half, wmma::col_major> bf[4];
                #pragma unroll
                for (int i = 0; i < 2; ++i)
                    wmma::load_matrix_sync(af[i], Qs + (warp * 32 + i * 16) * QK_LD + kk, QK_LD);
                #pragma unroll
                for (int j = 0; j < 4; ++j)
                    wmma::load_matrix_sync(bf[j], Ks + (j * 16) * QK_LD + kk, QK_LD);
                #pragma unroll
                for (int i = 0; i < 2; ++i)
                    #pragma unroll
                    for (int j = 0; j < 4; ++j)
                        wmma::mma_sync(sacc[i][j], af[i], bf[j], sacc[i][j]);
            }
            #pragma unroll
            for (int i = 0; i < 2; ++i)
                #pragma unroll
                for (int j = 0; j < 4; ++j)
                    wmma::store_matrix_sync(Ss + (warp * 32 + i * 16) * S_LD + j * 16,
                                            sacc[i][j], S_LD, wmma::mem_row_major);
        }
        __syncthreads();

        // softmax row r = tid
        {
            int r = tid;
            const float* brow = bias16 + ((size_t)head * 64 + r) * 64;
            float v[64];
            float mx = -1e30f;
            #pragma unroll
            for (int q = 0; q < 16; ++q) {
                float4 s = *(float4*)(Ss + r * S_LD + q * 4);
                float4 b = *(const float4*)(brow + q * 4);
                v[q*4+0] = s.x * ATTN_SCALE + b.x;
                v[q*4+1] = s.y * ATTN_SCALE + b.y;
                v[q*4+2] = s.z * ATTN_SCALE + b.z;
                v[q*4+3] = s.w * ATTN_SCALE + b.w;
                mx = fmaxf(mx, fmaxf(fmaxf(v[q*4+0], v[q*4+1]), fmaxf(v[q*4+2], v[q*4+3])));
            }
            float sum = 0.0f;
            #pragma unroll
            for (int m = 0; m < 64; ++m) { v[m] = __expf(v[m] - mx); sum += v[m]; }
            float inv = 1.0f / sum;
            __half* Ps = (__half*)Ss;
            #pragma unroll
            for (int q = 0; q < 8; ++q) {
                uint4 pk; __half2 hh;
                hh = __floats2half2_rn(v[q*8+0]*inv, v[q*8+1]*inv); pk.x = *(unsigned*)&hh;
                hh = __floats2half2_rn(v[q*8+2]*inv, v[q*8+3]*inv); pk.y = *(unsigned*)&hh;
                hh = __floats2half2_rn(v[q*8+4]*inv, v[q*8+5]*inv); pk.z = *(unsigned*)&hh;
                hh = __floats2half2_rn(v[q*8+6]*inv, v[q*8+7]*inv); pk.w = *(unsigned*)&hh;
                *(uint4*)(Ps + r * P_LDH + q * 8) = pk;
            }
        }
        __syncthreads();

        // O = P @ V  (64x32x64)
        {
            const __half* Ps = (const __half*)Ss;
            wmma::fragment<wmma::accumulator, 16, 16, 16, float> oacc[2][2];
            #pragma unroll
            for (int i = 0; i < 2; ++i)
                #pragma unroll
                for (int j = 0; j < 2; ++j)
                    wmma::fill_fragment(oacc[i][j], 0.0f);
            #pragma unroll
            for (int kk = 0; kk < 64; kk += 16) {
                wmma::fragment<wmma::matrix_a, 16, 16, 16, __half, wmma::row_major> af[2];
                wmma::fragment<wmma::matrix_b, 16, 16, 16, __half, wmma::row_major> bf[2];
                #pragma unroll
                for (int i = 0; i < 2; ++i)
                    wmma::load_matrix_sync(af[i], Ps + (warp * 32 + i * 16) * P_LDH + kk, P_LDH);
                #pragma unroll
                for (int j = 0; j < 2; ++j)
                    wmma::load_matrix_sync(bf[j], Vs + kk * QK_LD + j * 16, QK_LD);
                #pragma unroll
                for (int i = 0; i < 2; ++i)
                    #pragma unroll
                    for (int j = 0; j < 2; ++j)
                        wmma::mma_sync(oacc[i][j], af[i], bf[j], oacc[i][j]);
            }
            #pragma unroll
            for (int i = 0; i < 2; ++i)
                #pragma unroll
                for (int j = 0; j < 2; ++j)
                    wmma::store_matrix_sync(Ss + (warp * 32 + i * 16) * S_LD + j * 16,
                                            oacc[i][j], S_LD, wmma::mem_row_major);
        }
        __syncthreads();

        // write ctx
        {
            int r = tid;
            size_t ob = ((size_t)win * 64 + r) * CDIM + head * 32;
            #pragma unroll
            for (int q = 0; q < 4; ++q) {
                float4 a = *(float4*)(Ss + r * S_LD + q * 8);
                float4 b = *(float4*)(Ss + r * S_LD + q * 8 + 4);
                uint4 pk; __half2 hh;
                hh = __floats2half2_rn(a.x, a.y); pk.x = *(unsigned*)&hh;
                hh = __floats2half2_rn(a.z, a.w); pk.y = *(unsigned*)&hh;
                hh = __floats2half2_rn(b.x, b.y); pk.z = *(unsigned*)&hh;
                hh = __floats2half2_rn(b.z, b.w); pk.w = *(unsigned*)&hh;
                *(uint4*)(ctx + ob + q * 8) = pk;
            }
        }
        __syncthreads();   // Ss reuse barrier before next head
    }
}

// =====================================================================
extern "C" void kernel_launch(void* const* d_in, const int* in_sizes, int n_in,
                              void* d_out, int out_size)
{
    const float* x      = (const float*)d_in[0];
    const float* qkv_w  = (const float*)d_in[1];
    const float* qkv_b  = (const float*)d_in[2];
    const float* proj_w = (const float*)d_in[3];
    const float* proj_b = (const float*)d_in[4];
    const float* relt   = (const float*)d_in[5];
    const float* bn1g   = (const float*)d_in[6];
    const float* bn1b   = (const float*)d_in[7];
    const float* bn1m   = (const float*)d_in[8];
    const float* bn1v   = (const float*)d_in[9];
    const float* mlp_w1 = (const float*)d_in[10];
    const float* mlp_b1 = (const float*)d_in[11];
    const float* mlp_w2 = (const float*)d_in[12];
    const float* mlp_b2 = (const float*)d_in[13];
    const float* bn2g   = (const float*)d_in[14];
    const float* bn2b   = (const float*)d_in[15];
    const float* bn2m   = (const float*)d_in[16];
    const float* bn2v   = (const float*)d_in[17];
    float* out = (float*)d_out;

    __half *p_xw, *p_qkv, *p_ctx, *p_xn2, *p_h, *p_wqkv, *p_wproj, *p_w1, *p_w2;
    float  *p_x1, *p_bias;
    cudaGetSymbolAddress((void**)&p_xw,   g_xw);
    cudaGetSymbolAddress((void**)&p_qkv,  g_qkv);
    cudaGetSymbolAddress((void**)&p_ctx,  g_ctx);
    cudaGetSymbolAddress((void**)&p_x1,   g_x1);
    cudaGetSymbolAddress((void**)&p_xn2,  g_xn2);
    cudaGetSymbolAddress((void**)&p_h,    g_h);
    cudaGetSymbolAddress((void**)&p_wqkv, g_wqkv);
    cudaGetSymbolAddress((void**)&p_wproj,g_wproj);
    cudaGetSymbolAddress((void**)&p_w1,   g_w1);
    cudaGetSymbolAddress((void**)&p_w2,   g_w2);
    cudaGetSymbolAddress((void**)&p_bias, g_bias);

    cudaFuncSetAttribute(gemm_h<false, 4>, cudaFuncAttributeMaxDynamicSharedMemorySize, GEMM_SMEM);
    cudaFuncSetAttribute(gemm_h<false, 3>, cudaFuncAttributeMaxDynamicSharedMemorySize, GEMM_SMEM);
    cudaFuncSetAttribute(gemm_h<true, 1>,  cudaFuncAttributeMaxDynamicSharedMemorySize, GEMM_SMEM);
    cudaFuncSetAttribute(gemm_h<true, 2>,  cudaFuncAttributeMaxDynamicSharedMemorySize, GEMM_SMEM);

    // 1) BN1 + window partition, with fused weight-cvt + bias-expand aux blocks
    prep_kernel<<<NWIN + AUXBLK, 256>>>(x, bn1g, bn1b, bn1m, bn1v, p_xw, 1,
                                        qkv_w, proj_w, mlp_w1, mlp_w2,
                                        p_wqkv, p_wproj, p_w1, p_w2,
                                        relt, p_bias);

    // 2) QKV projection -> attention-friendly layout
    gemm_h<false, 4><<<dim3(QKVN / GBN, MTOT / GBM), NTHR, GEMM_SMEM>>>(
        p_xw, p_wqkv, qkv_b, p_qkv, nullptr, MTOT, QKVN, CDIM);

    // 3) windowed attention (tensor cores, double-buffered head pairs)
    attn_tc_kernel<<<NWIN * 8, 64>>>(p_qkv, p_bias, p_ctx);

    // 4) proj + window-reverse + x residual -> x1 (NCHW f32), fused
    gemm_h<false, 3><<<dim3(CDIM / GBN, MTOT / GBM), NTHR, GEMM_SMEM>>>(
        p_ctx, p_wproj, proj_b, p_x1, x, MTOT, CDIM, CDIM);

    // 5) BN2 + pixel-major transpose
    prep_kernel<<<NWIN, 256>>>(p_x1, bn2g, bn2b, bn2m, bn2v, p_xn2, 0,
                               nullptr, nullptr, nullptr, nullptr,
                               nullptr, nullptr, nullptr, nullptr,
                               nullptr, nullptr);

    // 6) FC1 + GELU
    gemm_h<true, 1><<<dim3(CDIM / GBN, MTOT / GBM), NTHR, GEMM_SMEM>>>(
        p_xn2, p_w1, mlp_b1, p_h, nullptr, MTOT, CDIM, CDIM);

    // 7) FC2 + bias + residual -> NCHW f32 output
    gemm_h<true, 2><<<dim3(CDIM / GBN, MTOT / GBM), NTHR, GEMM_SMEM>>>(
        p_h, p_w2, mlp_b2, out, p_x1, MTOT, CDIM, CDIM);
}